// round 3
// baseline (speedup 1.0000x reference)
#include <cuda_runtime.h>
#include <cstdint>

#define B_ 2
#define S_ 2048
#define D_ 512
#define V_ 32000
#define H_ 11
#define HP 12           // padded H stride
#define R_ (B_*S_)      // 4096 rows

// ---------------- scratch (device globals: allocation-free) ----------------
__device__ float g_emb[R_ * D_];                 // embeddings + pos
__device__ float g_h1 [R_ * D_];                 // block1 output
__device__ float g_h2 [R_ * D_];                 // block2 output
__device__ float g_q  [R_ * HP];
__device__ float g_k  [R_ * HP];
__device__ float g_v  [R_ * HP];
__device__ float g_att[(size_t)B_ * S_ * S_];    // attT[b][k][q]  (33.5 MB)
__device__ float g_part[4 * R_ * HP];            // att@v partials over 4 k-chunks

// ---------------- 1) embedding + positional encoding ----------------
__global__ void embed_kernel(const int* __restrict__ x, const float* __restrict__ tab) {
    int idx = blockIdx.x * 256 + threadIdx.x;        // [0, R_*D_)
    int d  = idx & (D_ - 1);
    int rs = idx >> 9;                               // row = b*S + s
    int s  = rs & (S_ - 1);
    int tok = x[rs];
    int e = d & ~1;                                  // even base index
    // denom = 10000^(2*e/512) => ang = s * 10000^(-e/256)
    float ang = (float)s * expf(-(float)e * (9.210340371976184f / 256.0f));
    float p = (d & 1) ? cosf(ang) : sinf(ang);
    g_emb[idx] = tab[(size_t)tok * D_ + d] + p;
}

// ---------------- 2) q/k/v projections (D=512 -> H=11 each) ----------------
__global__ void qkv_kernel(int phase,
                           const float* __restrict__ kw, const float* __restrict__ kb,
                           const float* __restrict__ qw, const float* __restrict__ qb,
                           const float* __restrict__ vw, const float* __restrict__ vb) {
    const float* src = phase ? g_h1 : g_emb;
    __shared__ float Esh[8 * D_];                    // 8 rows, 16 KB
    int r0 = blockIdx.x * 8;
    int tid = threadIdx.x;
    for (int i = tid; i < 8 * D_; i += 256) Esh[i] = src[r0 * D_ + i];
    __syncthreads();
    for (int t = tid; t < 8 * 33; t += 256) {
        int row = t / 33, o = t % 33;
        const float *W, *bb; float* dst;
        if (o < 11)      { W = kw; bb = kb; dst = g_k; }
        else if (o < 22) { W = qw; bb = qb; dst = g_q; }
        else             { W = vw; bb = vb; dst = g_v; }
        int h = o % 11;
        float sacc = bb[h];
        const float* er = &Esh[row * D_];
        #pragma unroll 8
        for (int c = 0; c < D_; c++) sacc += er[c] * W[c * H_ + h];
        dst[(r0 + row) * HP + h] = sacc;
    }
}

// ---------------- 3) scores + causal mask + softmax over QUERY axis ----------------
// One block per (k-column, batch). attT[b][k][q] = softmax_q(dot(Q[q],K[k]) | q>=k)
__global__ void scores_kernel() {
    int k = blockIdx.x, b = blockIdx.y;
    int tid = threadIdx.x;
    __shared__ float kv[H_];
    __shared__ float red[256];
    if (tid < H_) kv[tid] = g_k[(b * S_ + k) * HP + tid];
    __syncthreads();

    float dloc[8];
    float m = -1e30f;
    int cnt = 0;
    for (int q = k + tid; q < S_; q += 256) {
        const float* qp = &g_q[(b * S_ + q) * HP];
        float d = 0.f;
        #pragma unroll
        for (int h = 0; h < H_; h++) d += qp[h] * kv[h];
        dloc[cnt++] = d;
        m = fmaxf(m, d);
    }
    red[tid] = m; __syncthreads();
    #pragma unroll
    for (int s = 128; s > 0; s >>= 1) {
        if (tid < s) red[tid] = fmaxf(red[tid], red[tid + s]);
        __syncthreads();
    }
    float M = red[0]; __syncthreads();

    float ssum = 0.f;
    for (int i = 0; i < cnt; i++) { dloc[i] = expf(dloc[i] - M); ssum += dloc[i]; }
    red[tid] = ssum; __syncthreads();
    #pragma unroll
    for (int s = 128; s > 0; s >>= 1) {
        if (tid < s) red[tid] += red[tid + s];
        __syncthreads();
    }
    float inv = 1.0f / red[0];

    size_t rowbase = ((size_t)b * S_ + k) * S_;
    cnt = 0;
    for (int q = k + tid; q < S_; q += 256) g_att[rowbase + q] = dloc[cnt++] * inv;
    for (int q = tid; q < k; q += 256)      g_att[rowbase + q] = 0.f;   // masked region
}

// ---------------- 4) res = att @ v  (per k-chunk partials, no atomics) ----------------
// grid (qtile=16, kchunk=4, b=2), 128 threads; thread owns one q.
__global__ void attv_kernel() {
    int qt = blockIdx.x, kc = blockIdx.y, b = blockIdx.z;
    int tid = threadIdx.x;
    __shared__ float vsh[512 * HP];                  // 24 KB
    int k0 = kc * 512;
    const float* vbase = &g_v[(b * S_ + k0) * HP];
    for (int i = tid; i < 512 * HP; i += 128) vsh[i] = vbase[i];
    __syncthreads();

    int q = qt * 128 + tid;
    float acc[H_];
    #pragma unroll
    for (int h = 0; h < H_; h++) acc[h] = 0.f;

    size_t attbase = ((size_t)b * S_ + k0) * S_ + q;
    for (int kk = 0; kk < 512; kk++) {
        float a = g_att[attbase + (size_t)kk * S_];
        const float* vr = &vsh[kk * HP];
        #pragma unroll
        for (int h = 0; h < H_; h++) acc[h] += a * vr[h];
    }
    float* dst = &g_part[((kc * R_) + b * S_ + q) * HP];
    #pragma unroll
    for (int h = 0; h < H_; h++) dst[h] = acc[h];
}

// ---------------- 5) out = res @ fw + fb  (sums the 4 partials) ----------------
__global__ void ff_kernel(int phase, const float* __restrict__ fw, const float* __restrict__ fb) {
    float* dst = phase ? g_h2 : g_h1;
    int idx = blockIdx.x * 256 + threadIdx.x;        // [0, R_*D_)
    int r = idx >> 9, d = idx & (D_ - 1);
    float resv[H_];
    #pragma unroll
    for (int h = 0; h < H_; h++)
        resv[h] = g_part[(0 * R_ + r) * HP + h] + g_part[(1 * R_ + r) * HP + h]
                + g_part[(2 * R_ + r) * HP + h] + g_part[(3 * R_ + r) * HP + h];
    float sacc = fb[d];
    #pragma unroll
    for (int h = 0; h < H_; h++) sacc += resv[h] * fw[h * D_ + d];
    dst[idx] = sacc;
}

// ---------------- 6) final vocab GEMM: [4096,512] @ [512,32000] + bias ----------------
#define BM 128
#define BN 128
#define BK 8
#define TM 8
#define TN 8
__global__ __launch_bounds__(256, 2)
void gemm_kernel(const float* __restrict__ Bmat, const float* __restrict__ bias,
                 float* __restrict__ C) {
    __shared__ float As[BK][BM];
    __shared__ float Bs[BK][BN];
    const float* A = g_h2;
    int tid = threadIdx.x;
    int colBase = blockIdx.x * BN;
    int rowBase = blockIdx.y * BM;

    int arow = tid >> 1, acol = (tid & 1) * 4;       // A tile: 128x8 via float4
    int brow = tid >> 5, bcol = (tid & 31) * 4;      // B tile: 8x128 via float4
    int tx = tid & 15, ty = tid >> 4;

    float acc[TM][TN];
    #pragma unroll
    for (int i = 0; i < TM; i++)
        #pragma unroll
        for (int j = 0; j < TN; j++) acc[i][j] = 0.f;

    for (int k0 = 0; k0 < D_; k0 += BK) {
        float4 av = *(const float4*)&A[(rowBase + arow) * D_ + k0 + acol];
        As[acol + 0][arow] = av.x; As[acol + 1][arow] = av.y;
        As[acol + 2][arow] = av.z; As[acol + 3][arow] = av.w;
        float4 bv = *(const float4*)&Bmat[(size_t)(k0 + brow) * V_ + colBase + bcol];
        *(float4*)&Bs[brow][bcol] = bv;
        __syncthreads();

        #pragma unroll
        for (int kk = 0; kk < BK; kk++) {
            float a[TM], bb[TN];
            #pragma unroll
            for (int i = 0; i < TM; i++) a[i] = As[kk][ty * TM + i];
            #pragma unroll
            for (int j = 0; j < TN; j++) bb[j] = Bs[kk][tx * TN + j];
            #pragma unroll
            for (int i = 0; i < TM; i++)
                #pragma unroll
                for (int j = 0; j < TN; j++) acc[i][j] += a[i] * bb[j];
        }
        __syncthreads();
    }

    #pragma unroll
    for (int i = 0; i < TM; i++) {
        int r = rowBase + ty * TM + i;
        int c0 = colBase + tx * TN;
        size_t base = (size_t)r * V_ + c0;
        #pragma unroll
        for (int j = 0; j < TN; j += 4) {
            float4 o;
            o.x = acc[i][j + 0] + __ldg(&bias[c0 + j + 0]);
            o.y = acc[i][j + 1] + __ldg(&bias[c0 + j + 1]);
            o.z = acc[i][j + 2] + __ldg(&bias[c0 + j + 2]);
            o.w = acc[i][j + 3] + __ldg(&bias[c0 + j + 3]);
            *(float4*)&C[base + j] = o;
        }
    }
}

// ---------------- launch ----------------
extern "C" void kernel_launch(void* const* d_in, const int* in_sizes, int n_in,
                              void* d_out, int out_size) {
    const int*   x    = (const int*)d_in[0];
    const float* tab  = (const float*)d_in[1];
    const float* k1w  = (const float*)d_in[2];
    const float* k1b  = (const float*)d_in[3];
    const float* q1w  = (const float*)d_in[4];
    const float* q1b  = (const float*)d_in[5];
    const float* v1w  = (const float*)d_in[6];
    const float* v1b  = (const float*)d_in[7];
    const float* f1w  = (const float*)d_in[8];
    const float* f1b  = (const float*)d_in[9];
    const float* k2w  = (const float*)d_in[10];
    const float* k2b  = (const float*)d_in[11];
    const float* q2w  = (const float*)d_in[12];
    const float* q2b  = (const float*)d_in[13];
    const float* v2w  = (const float*)d_in[14];
    const float* v2b  = (const float*)d_in[15];
    const float* f2w  = (const float*)d_in[16];
    const float* f2b  = (const float*)d_in[17];
    const float* outw = (const float*)d_in[18];
    const float* outb = (const float*)d_in[19];
    float* out = (float*)d_out;

    embed_kernel<<<(R_ * D_) / 256, 256>>>(x, tab);

    // attention block 1: g_emb -> g_h1
    qkv_kernel<<<R_ / 8, 256>>>(0, k1w, k1b, q1w, q1b, v1w, v1b);
    scores_kernel<<<dim3(S_, B_), 256>>>();
    attv_kernel<<<dim3(16, 4, 2), 128>>>();
    ff_kernel<<<(R_ * D_) / 256, 256>>>(0, f1w, f1b);

    // attention block 2: g_h1 -> g_h2
    qkv_kernel<<<R_ / 8, 256>>>(1, k2w, k2b, q2w, q2b, v2w, v2b);
    scores_kernel<<<dim3(S_, B_), 256>>>();
    attv_kernel<<<dim3(16, 4, 2), 128>>>();
    ff_kernel<<<(R_ * D_) / 256, 256>>>(1, f2w, f2b);

    // final vocab projection
    gemm_kernel<<<dim3(V_ / BN, R_ / BM), 256>>>(outw, outb, out);
}

// round 5
// speedup vs baseline: 1.9188x; 1.9188x over previous
#include <cuda_runtime.h>
#include <cuda_bf16.h>
#include <cstdint>

#define B_ 2
#define S_ 2048
#define D_ 512
#define V_ 32000
#define H_ 11
#define HP 12           // padded H stride
#define R_ (B_*S_)      // 4096 rows
#define KCH 16          // attv k-chunks (128 keys each)

// ---------------- scratch (device globals: allocation-free) ----------------
__device__ float g_emb[R_ * D_];
__device__ float g_h1 [R_ * D_];
__device__ float g_h2 [R_ * D_];
__device__ float g_q  [R_ * HP];
__device__ float g_k  [R_ * HP];
__device__ float g_v  [R_ * HP];
__device__ float g_att[(size_t)B_ * S_ * S_];        // attT[b][k][q]
__device__ float g_part[KCH * R_ * HP];              // att@v partials
__device__ float g_res [R_ * HP];                    // summed partials
__device__ __nv_bfloat16 g_a_hi[R_ * D_];            // split A for final GEMM
__device__ __nv_bfloat16 g_a_lo[R_ * D_];
__device__ __nv_bfloat16 g_bt_hi[(size_t)V_ * D_];   // out_w^T split, [v][k]
__device__ __nv_bfloat16 g_bt_lo[(size_t)V_ * D_];

// ---------------- 1) embedding + positional encoding ----------------
__global__ void embed_kernel(const int* __restrict__ x, const float* __restrict__ tab) {
    int idx = blockIdx.x * 256 + threadIdx.x;
    int d  = idx & (D_ - 1);
    int rs = idx >> 9;
    int s  = rs & (S_ - 1);
    int tok = x[rs];
    int e = d & ~1;
    float ang = (float)s * expf(-(float)e * (9.210340371976184f / 256.0f));
    float p = (d & 1) ? cosf(ang) : sinf(ang);
    g_emb[idx] = tab[(size_t)tok * D_ + d] + p;
}

// ---------------- 2) q/k/v projections ----------------
__global__ void qkv_kernel(int phase,
                           const float* __restrict__ kw, const float* __restrict__ kb,
                           const float* __restrict__ qw, const float* __restrict__ qb,
                           const float* __restrict__ vw, const float* __restrict__ vb) {
    const float* src = phase ? g_h1 : g_emb;
    __shared__ float Esh[8 * D_];
    int r0 = blockIdx.x * 8;
    int tid = threadIdx.x;
    for (int i = tid; i < 8 * D_; i += 256) Esh[i] = src[r0 * D_ + i];
    __syncthreads();
    for (int t = tid; t < 8 * 33; t += 256) {
        int row = t / 33, o = t % 33;
        const float *W, *bb; float* dst;
        if (o < 11)      { W = kw; bb = kb; dst = g_k; }
        else if (o < 22) { W = qw; bb = qb; dst = g_q; }
        else             { W = vw; bb = vb; dst = g_v; }
        int h = o % 11;
        float sacc = bb[h];
        const float* er = &Esh[row * D_];
        #pragma unroll 8
        for (int c = 0; c < D_; c++) sacc += er[c] * W[c * H_ + h];
        dst[(r0 + row) * HP + h] = sacc;
    }
}

// ---------------- 3) scores + causal mask + softmax over QUERY axis ----------------
__global__ void scores_kernel() {
    int k = blockIdx.x, b = blockIdx.y;
    int tid = threadIdx.x;
    __shared__ float kv[H_];
    __shared__ float red[256];
    if (tid < H_) kv[tid] = g_k[(b * S_ + k) * HP + tid];
    __syncthreads();

    float dloc[8];
    float m = -1e30f;
    int cnt = 0;
    for (int q = k + tid; q < S_; q += 256) {
        const float* qp = &g_q[(b * S_ + q) * HP];
        float d = 0.f;
        #pragma unroll
        for (int h = 0; h < H_; h++) d += qp[h] * kv[h];
        dloc[cnt++] = d;
        m = fmaxf(m, d);
    }
    red[tid] = m; __syncthreads();
    #pragma unroll
    for (int s = 128; s > 0; s >>= 1) {
        if (tid < s) red[tid] = fmaxf(red[tid], red[tid + s]);
        __syncthreads();
    }
    float M = red[0]; __syncthreads();

    float ssum = 0.f;
    for (int i = 0; i < cnt; i++) { dloc[i] = expf(dloc[i] - M); ssum += dloc[i]; }
    red[tid] = ssum; __syncthreads();
    #pragma unroll
    for (int s = 128; s > 0; s >>= 1) {
        if (tid < s) red[tid] += red[tid + s];
        __syncthreads();
    }
    float inv = 1.0f / red[0];

    size_t rowbase = ((size_t)b * S_ + k) * S_;
    cnt = 0;
    for (int q = k + tid; q < S_; q += 256) g_att[rowbase + q] = dloc[cnt++] * inv;
    for (int q = tid; q < k; q += 256)      g_att[rowbase + q] = 0.f;
}

// ---------------- 4) res = att @ v  (16 k-chunks, causal early-out) ----------------
__global__ void attv_kernel() {
    int qt = blockIdx.x, kc = blockIdx.y, b = blockIdx.z;
    int tid = threadIdx.x;
    int q = qt * 128 + tid;
    float* dst = &g_part[((kc * R_) + b * S_ + q) * HP];
    if (kc > qt) {                       // fully masked chunk
        #pragma unroll
        for (int h = 0; h < H_; h++) dst[h] = 0.f;
        return;
    }
    __shared__ float vsh[128 * HP];
    int k0 = kc * 128;
    const float* vbase = &g_v[(b * S_ + k0) * HP];
    for (int i = tid; i < 128 * HP; i += 128) vsh[i] = vbase[i];
    __syncthreads();

    float acc[H_];
    #pragma unroll
    for (int h = 0; h < H_; h++) acc[h] = 0.f;

    size_t attbase = ((size_t)b * S_ + k0) * S_ + q;
    for (int kk = 0; kk < 128; kk++) {
        float a = g_att[attbase + (size_t)kk * S_];
        const float* vr = &vsh[kk * HP];
        #pragma unroll
        for (int h = 0; h < H_; h++) acc[h] += a * vr[h];
    }
    #pragma unroll
    for (int h = 0; h < H_; h++) dst[h] = acc[h];
}

// ---------------- 4b) sum partials ----------------
__global__ void reduce_part_kernel() {
    int idx = blockIdx.x * 256 + threadIdx.x;        // [0, R_*HP)
    float s = 0.f;
    #pragma unroll
    for (int p = 0; p < KCH; p++) s += g_part[p * R_ * HP + idx];
    g_res[idx] = s;
}

// ---------------- 5) out = res @ fw + fb ----------------
__global__ void ff_kernel(int phase, const float* __restrict__ fw, const float* __restrict__ fb) {
    float* dst = phase ? g_h2 : g_h1;
    int idx = blockIdx.x * 256 + threadIdx.x;
    int r = idx >> 9, d = idx & (D_ - 1);
    float sacc = fb[d];
    #pragma unroll
    for (int h = 0; h < H_; h++) sacc += g_res[r * HP + h] * fw[h * D_ + d];
    dst[idx] = sacc;
}

// ---------------- 6a) split A (g_h2) into bf16 hi/lo ----------------
__global__ void conv_a_kernel() {
    int idx = blockIdx.x * 256 + threadIdx.x;        // [0, R_*D_)
    float a = g_h2[idx];
    __nv_bfloat16 hi = __float2bfloat16(a);
    g_a_hi[idx] = hi;
    g_a_lo[idx] = __float2bfloat16(a - __bfloat162float(hi));
}

// ---------------- 6b) transpose+split out_w [k][v] -> bt[v][k] bf16 hi/lo ----------------
__global__ void conv_b_kernel(const float* __restrict__ outw) {
    __shared__ float t[32][33];
    int v0 = blockIdx.x * 32, k0 = blockIdx.y * 32;
    int tx = threadIdx.x, ty = threadIdx.y;          // 32 x 8
    #pragma unroll
    for (int j = 0; j < 4; j++) {
        int k = k0 + ty + j * 8;
        t[ty + j * 8][tx] = outw[(size_t)k * V_ + v0 + tx];
    }
    __syncthreads();
    #pragma unroll
    for (int j = 0; j < 4; j++) {
        int v = v0 + ty + j * 8;
        float val = t[tx][ty + j * 8];               // = outw[k0+tx][v]
        __nv_bfloat16 hi = __float2bfloat16(val);
        size_t o = (size_t)v * D_ + k0 + tx;
        g_bt_hi[o] = hi;
        g_bt_lo[o] = __float2bfloat16(val - __bfloat162float(hi));
    }
}

// ---------------- 6c) mma.sync split-bf16 GEMM: C[4096,32000] = A@B^T + bias ----
// Tile 128x128, K-chunk 32, 3-stage cp.async pipeline, 8 warps (warp tile 32x64).
// 3 terms: Ah*Bh + Al*Bh + Ah*Bl (dropped Al*Bl ~ 2^-18 relative).
#define LDP 40            // padded smem row stride in bf16 (80B -> ldmatrix conflict-free)
#define TILE_BYTES (128 * LDP * 2)   // 10240
#define STG_A_HI 0
#define STG_A_LO (1 * TILE_BYTES)
#define STG_B_HI (2 * TILE_BYTES)
#define STG_B_LO (3 * TILE_BYTES)
#define STG_SZ   (4 * TILE_BYTES)    // 40960
#define NSTAGE 3
#define NCHUNK (D_ / 32)             // 16

__device__ __forceinline__ uint32_t smem_u32(const void* p) {
    uint32_t r;
    asm("{ .reg .u64 t; cvta.to.shared.u64 t, %1; cvt.u32.u64 %0, t; }"
        : "=r"(r) : "l"(p));
    return r;
}
__device__ __forceinline__ void cpa16(uint32_t saddr, const void* gaddr) {
    asm volatile("cp.async.cg.shared.global [%0], [%1], 16;" :: "r"(saddr), "l"(gaddr));
}
__device__ __forceinline__ void cpa_commit() {
    asm volatile("cp.async.commit_group;" ::: "memory");
}
__device__ __forceinline__ void cpa_wait2() {
    asm volatile("cp.async.wait_group 2;" ::: "memory");
}
__device__ __forceinline__ void ldmatrix4(uint32_t* r, uint32_t addr) {
    asm volatile("ldmatrix.sync.aligned.m8n8.x4.shared.b16 {%0,%1,%2,%3}, [%4];"
                 : "=r"(r[0]), "=r"(r[1]), "=r"(r[2]), "=r"(r[3]) : "r"(addr));
}
__device__ __forceinline__ void mma16816(float* c, const uint32_t* a, uint32_t b0, uint32_t b1) {
    asm volatile(
        "mma.sync.aligned.m16n8k16.row.col.f32.bf16.bf16.f32 "
        "{%0,%1,%2,%3}, {%4,%5,%6,%7}, {%8,%9}, {%0,%1,%2,%3};"
        : "+f"(c[0]), "+f"(c[1]), "+f"(c[2]), "+f"(c[3])
        : "r"(a[0]), "r"(a[1]), "r"(a[2]), "r"(a[3]), "r"(b0), "r"(b1));
}

__global__ __launch_bounds__(256, 1)
void gemm_mma_kernel(const float* __restrict__ bias, float* __restrict__ C) {
    extern __shared__ __align__(16) char smem[];
    uint32_t sb = smem_u32(smem);
    int tid = threadIdx.x;
    int wid = tid >> 5, lid = tid & 31;
    int rowBase = blockIdx.x * 128;
    int colBase = blockIdx.y * 128;

    const __nv_bfloat16* srcs[4] = {
        g_a_hi + (size_t)rowBase * D_,
        g_a_lo + (size_t)rowBase * D_,
        g_bt_hi + (size_t)colBase * D_,
        g_bt_lo + (size_t)colBase * D_,
    };

    // ---- async load of one 4-tile chunk into stage s ----
    auto load_chunk = [&](int c, int s) {
        int k0 = c * 32;
        uint32_t stg = sb + (uint32_t)s * STG_SZ;
        #pragma unroll
        for (int t = 0; t < 4; t++) {
            const __nv_bfloat16* src = srcs[t] + k0;
            uint32_t base = stg + (uint32_t)t * TILE_BYTES;
            #pragma unroll
            for (int it = 0; it < 2; it++) {
                int idx = tid + it * 256;             // [0,512)
                int r = idx >> 2, ch = idx & 3;
                cpa16(base + r * (LDP * 2) + ch * 16, src + (size_t)r * D_ + ch * 8);
            }
        }
    };

    load_chunk(0, 0); cpa_commit();
    load_chunk(1, 1); cpa_commit();

    int warpM = (wid & 3) * 32;       // 4 m-warps
    int warpN = (wid >> 2) * 64;      // 2 n-warps
    int lrow = lid & 15;
    int lk = (lid >> 4) * 8;

    float acc[2][8][4];
    #pragma unroll
    for (int i = 0; i < 2; i++)
        #pragma unroll
        for (int j = 0; j < 8; j++)
            #pragma unroll
            for (int v = 0; v < 4; v++) acc[i][j][v] = 0.f;

    #pragma unroll 1
    for (int c = 0; c < NCHUNK; c++) {
        if (c + 2 < NCHUNK) load_chunk(c + 2, (c + 2) % NSTAGE);
        cpa_commit();
        cpa_wait2();
        __syncthreads();

        uint32_t stg = sb + (uint32_t)(c % NSTAGE) * STG_SZ;
        #pragma unroll
        for (int term = 0; term < 3; term++) {
            uint32_t aoff = stg + (term == 1 ? STG_A_LO : STG_A_HI);
            uint32_t boff = stg + (term == 2 ? STG_B_LO : STG_B_HI);
            #pragma unroll
            for (int k16 = 0; k16 < 2; k16++) {
                uint32_t a[2][4];
                #pragma unroll
                for (int mi = 0; mi < 2; mi++)
                    ldmatrix4(a[mi], aoff + ((warpM + mi * 16 + lrow) * LDP + k16 * 16 + lk) * 2);
                uint32_t b[4][4];
                #pragma unroll
                for (int ni = 0; ni < 4; ni++)
                    ldmatrix4(b[ni], boff + ((warpN + ni * 16 + lrow) * LDP + k16 * 16 + lk) * 2);
                #pragma unroll
                for (int mi = 0; mi < 2; mi++)
                    #pragma unroll
                    for (int nj = 0; nj < 8; nj++) {
                        uint32_t b0 = (nj & 1) ? b[nj >> 1][1] : b[nj >> 1][0];
                        uint32_t b1 = (nj & 1) ? b[nj >> 1][3] : b[nj >> 1][2];
                        mma16816(acc[mi][nj], a[mi], b0, b1);
                    }
            }
        }
        __syncthreads();
    }

    // ---- epilogue: direct stores with bias ----
    int g = lid >> 2, tig = lid & 3;
    #pragma unroll
    for (int mi = 0; mi < 2; mi++) {
        #pragma unroll
        for (int nj = 0; nj < 8; nj++) {
            int row = rowBase + warpM + mi * 16 + g;
            int col = colBase + warpN + nj * 8 + tig * 2;
            float2 bv = *(const float2*)&bias[col];
            float2 o0 = { acc[mi][nj][0] + bv.x, acc[mi][nj][1] + bv.y };
            float2 o1 = { acc[mi][nj][2] + bv.x, acc[mi][nj][3] + bv.y };
            *(float2*)&C[(size_t)row * V_ + col] = o0;
            *(float2*)&C[(size_t)(row + 8) * V_ + col] = o1;
        }
    }
}

// ---------------- launch ----------------
extern "C" void kernel_launch(void* const* d_in, const int* in_sizes, int n_in,
                              void* d_out, int out_size) {
    const int*   x    = (const int*)d_in[0];
    const float* tab  = (const float*)d_in[1];
    const float* k1w  = (const float*)d_in[2];
    const float* k1b  = (const float*)d_in[3];
    const float* q1w  = (const float*)d_in[4];
    const float* q1b  = (const float*)d_in[5];
    const float* v1w  = (const float*)d_in[6];
    const float* v1b  = (const float*)d_in[7];
    const float* f1w  = (const float*)d_in[8];
    const float* f1b  = (const float*)d_in[9];
    const float* k2w  = (const float*)d_in[10];
    const float* k2b  = (const float*)d_in[11];
    const float* q2w  = (const float*)d_in[12];
    const float* q2b  = (const float*)d_in[13];
    const float* v2w  = (const float*)d_in[14];
    const float* v2b  = (const float*)d_in[15];
    const float* f2w  = (const float*)d_in[16];
    const float* f2b  = (const float*)d_in[17];
    const float* outw = (const float*)d_in[18];
    const float* outb = (const float*)d_in[19];
    float* out = (float*)d_out;

    cudaFuncSetAttribute(gemm_mma_kernel, cudaFuncAttributeMaxDynamicSharedMemorySize,
                         NSTAGE * STG_SZ);

    // out_w transpose+split is independent of everything upstream
    conv_b_kernel<<<dim3(V_ / 32, D_ / 32), dim3(32, 8)>>>(outw);

    embed_kernel<<<(R_ * D_) / 256, 256>>>(x, tab);

    // attention block 1: g_emb -> g_h1
    qkv_kernel<<<R_ / 8, 256>>>(0, k1w, k1b, q1w, q1b, v1w, v1b);
    scores_kernel<<<dim3(S_, B_), 256>>>();
    attv_kernel<<<dim3(16, KCH, 2), 128>>>();
    reduce_part_kernel<<<(R_ * HP) / 256, 256>>>();
    ff_kernel<<<(R_ * D_) / 256, 256>>>(0, f1w, f1b);

    // attention block 2: g_h1 -> g_h2
    qkv_kernel<<<R_ / 8, 256>>>(1, k2w, k2b, q2w, q2b, v2w, v2b);
    scores_kernel<<<dim3(S_, B_), 256>>>();
    attv_kernel<<<dim3(16, KCH, 2), 128>>>();
    reduce_part_kernel<<<(R_ * HP) / 256, 256>>>();
    ff_kernel<<<(R_ * D_) / 256, 256>>>(1, f2w, f2b);

    // final vocab projection on tensor cores (legacy HMMA path)
    conv_a_kernel<<<(R_ * D_) / 256, 256>>>();
    gemm_mma_kernel<<<dim3(R_ / 128, V_ / 128), 256, NSTAGE * STG_SZ>>>(outb, out);
}

// round 6
// speedup vs baseline: 2.0806x; 1.0843x over previous
#include <cuda_runtime.h>
#include <cuda_bf16.h>
#include <cstdint>

#define B_ 2
#define S_ 2048
#define D_ 512
#define V_ 32000
#define H_ 11
#define HP 12           // padded H stride
#define R_ (B_*S_)      // 4096 rows
#define KCH 16          // attv k-chunks (128 keys each)

// ---------------- scratch (device globals: allocation-free) ----------------
__device__ float g_emb[R_ * D_];
__device__ float g_h1 [R_ * D_];
__device__ float g_q  [R_ * HP];
__device__ float g_k  [R_ * HP];
__device__ float g_v  [R_ * HP];
__device__ float g_att[(size_t)B_ * S_ * S_];        // attT[b][k][q]
__device__ float g_part[KCH * R_ * HP];              // att@v partials
__device__ float g_res [R_ * HP];                    // summed partials
__device__ __nv_bfloat16 g_a_hi[R_ * D_];            // split A for final GEMM
__device__ __nv_bfloat16 g_a_lo[R_ * D_];
__device__ __nv_bfloat16 g_bt_hi[(size_t)V_ * D_];   // out_w^T split, [v][k]
__device__ __nv_bfloat16 g_bt_lo[(size_t)V_ * D_];

// ---------------- 1) embedding + positional encoding ----------------
__global__ void embed_kernel(const int* __restrict__ x, const float* __restrict__ tab) {
    int idx = blockIdx.x * 256 + threadIdx.x;
    int d  = idx & (D_ - 1);
    int rs = idx >> 9;
    int s  = rs & (S_ - 1);
    int tok = x[rs];
    int e = d & ~1;
    float ang = (float)s * expf(-(float)e * (9.210340371976184f / 256.0f));
    float p = (d & 1) ? cosf(ang) : sinf(ang);
    g_emb[idx] = tab[(size_t)tok * D_ + d] + p;
}

// ---------------- 2) q/k/v projections ----------------
__global__ void qkv_kernel(int phase,
                           const float* __restrict__ kw, const float* __restrict__ kb,
                           const float* __restrict__ qw, const float* __restrict__ qb,
                           const float* __restrict__ vw, const float* __restrict__ vb) {
    const float* src = phase ? g_h1 : g_emb;
    __shared__ float Esh[8 * D_];
    int r0 = blockIdx.x * 8;
    int tid = threadIdx.x;
    for (int i = tid; i < 8 * D_; i += 256) Esh[i] = src[r0 * D_ + i];
    __syncthreads();
    for (int t = tid; t < 8 * 33; t += 256) {
        int row = t / 33, o = t % 33;
        const float *W, *bb; float* dst;
        if (o < 11)      { W = kw; bb = kb; dst = g_k; }
        else if (o < 22) { W = qw; bb = qb; dst = g_q; }
        else             { W = vw; bb = vb; dst = g_v; }
        int h = o % 11;
        float sacc = bb[h];
        const float* er = &Esh[row * D_];
        #pragma unroll 8
        for (int c = 0; c < D_; c++) sacc += er[c] * W[c * H_ + h];
        dst[(r0 + row) * HP + h] = sacc;
    }
}

// ---------------- 3) scores + causal mask + softmax over QUERY axis ----------------
__global__ void scores_kernel() {
    int k = blockIdx.x, b = blockIdx.y;
    int tid = threadIdx.x;
    __shared__ float kv[H_];
    __shared__ float red[256];
    if (tid < H_) kv[tid] = g_k[(b * S_ + k) * HP + tid];
    __syncthreads();

    float dloc[8];
    float m = -1e30f;
    int cnt = 0;
    for (int q = k + tid; q < S_; q += 256) {
        const float* qp = &g_q[(b * S_ + q) * HP];
        float d = 0.f;
        #pragma unroll
        for (int h = 0; h < H_; h++) d += qp[h] * kv[h];
        dloc[cnt++] = d;
        m = fmaxf(m, d);
    }
    red[tid] = m; __syncthreads();
    #pragma unroll
    for (int s = 128; s > 0; s >>= 1) {
        if (tid < s) red[tid] = fmaxf(red[tid], red[tid + s]);
        __syncthreads();
    }
    float M = red[0]; __syncthreads();

    float ssum = 0.f;
    for (int i = 0; i < cnt; i++) { dloc[i] = expf(dloc[i] - M); ssum += dloc[i]; }
    red[tid] = ssum; __syncthreads();
    #pragma unroll
    for (int s = 128; s > 0; s >>= 1) {
        if (tid < s) red[tid] += red[tid + s];
        __syncthreads();
    }
    float inv = 1.0f / red[0];

    size_t rowbase = ((size_t)b * S_ + k) * S_;
    cnt = 0;
    for (int q = k + tid; q < S_; q += 256) g_att[rowbase + q] = dloc[cnt++] * inv;
    for (int q = tid; q < k; q += 256)      g_att[rowbase + q] = 0.f;
}

// ---------------- 4) res = att @ v  (16 k-chunks, causal early-out) ----------------
__global__ void attv_kernel() {
    int qt = blockIdx.x, kc = blockIdx.y, b = blockIdx.z;
    int tid = threadIdx.x;
    int q = qt * 128 + tid;
    float* dst = &g_part[((kc * R_) + b * S_ + q) * HP];
    if (kc > qt) {                       // fully masked chunk
        #pragma unroll
        for (int h = 0; h < H_; h++) dst[h] = 0.f;
        return;
    }
    __shared__ float vsh[128 * HP];
    int k0 = kc * 128;
    const float* vbase = &g_v[(b * S_ + k0) * HP];
    for (int i = tid; i < 128 * HP; i += 128) vsh[i] = vbase[i];
    __syncthreads();

    float acc[H_];
    #pragma unroll
    for (int h = 0; h < H_; h++) acc[h] = 0.f;

    size_t attbase = ((size_t)b * S_ + k0) * S_ + q;
    for (int kk = 0; kk < 128; kk++) {
        float a = g_att[attbase + (size_t)kk * S_];
        const float* vr = &vsh[kk * HP];
        #pragma unroll
        for (int h = 0; h < H_; h++) acc[h] += a * vr[h];
    }
    #pragma unroll
    for (int h = 0; h < H_; h++) dst[h] = acc[h];
}

// ---------------- 4b) sum partials ----------------
__global__ void reduce_part_kernel() {
    int idx = blockIdx.x * 256 + threadIdx.x;        // [0, R_*HP)
    float s = 0.f;
    #pragma unroll
    for (int p = 0; p < KCH; p++) s += g_part[p * R_ * HP + idx];
    g_res[idx] = s;
}

// ---------------- 5) out = res @ fw + fb ----------------
// phase 0: write fp32 to g_h1. phase 1: write bf16 hi/lo split directly (GEMM input).
__global__ void ff_kernel(int phase, const float* __restrict__ fw, const float* __restrict__ fb) {
    int idx = blockIdx.x * 256 + threadIdx.x;
    int r = idx >> 9, d = idx & (D_ - 1);
    float sacc = fb[d];
    #pragma unroll
    for (int h = 0; h < H_; h++) sacc += g_res[r * HP + h] * fw[h * D_ + d];
    if (phase == 0) {
        g_h1[idx] = sacc;
    } else {
        __nv_bfloat16 hi = __float2bfloat16(sacc);
        g_a_hi[idx] = hi;
        g_a_lo[idx] = __float2bfloat16(sacc - __bfloat162float(hi));
    }
}

// ---------------- 6a) transpose+split out_w [k][v] -> bt[v][k] bf16 hi/lo ----------------
__global__ void conv_b_kernel(const float* __restrict__ outw) {
    __shared__ float t[32][33];
    int v0 = blockIdx.x * 32, k0 = blockIdx.y * 32;
    int tx = threadIdx.x, ty = threadIdx.y;          // 32 x 8
    #pragma unroll
    for (int j = 0; j < 4; j++) {
        int k = k0 + ty + j * 8;
        t[ty + j * 8][tx] = outw[(size_t)k * V_ + v0 + tx];
    }
    __syncthreads();
    #pragma unroll
    for (int j = 0; j < 4; j++) {
        int v = v0 + ty + j * 8;
        float val = t[tx][ty + j * 8];               // = outw[k0+tx][v]
        __nv_bfloat16 hi = __float2bfloat16(val);
        size_t o = (size_t)v * D_ + k0 + tx;
        g_bt_hi[o] = hi;
        g_bt_lo[o] = __float2bfloat16(val - __bfloat162float(hi));
    }
}

// ---------------- 6b) mma.sync split-bf16 GEMM: C[4096,32000] = A@B^T + bias ----
// Tile 128x256, K-chunk 32, 3-stage cp.async pipeline, 8 warps (warp tile 64x64).
// 3 terms: Ah*Bh + Al*Bh + Ah*Bl (dropped Al*Bl ~ 2^-18 relative).
#define LDP 40                         // padded smem row stride in bf16 (80B)
#define ROWB (LDP * 2)                 // 80 bytes per row
#define A_ROWS 128
#define B_ROWS 256
#define A_LO_O (A_ROWS * ROWB)         // 10240
#define B_HI_O (2 * A_ROWS * ROWB)     // 20480
#define B_LO_O (B_HI_O + B_ROWS * ROWB)// 40960
#define STG_SZ (B_LO_O + B_ROWS * ROWB)// 61440
#define NSTAGE 3
#define NCHUNK (D_ / 32)               // 16

__device__ __forceinline__ uint32_t smem_u32(const void* p) {
    uint32_t r;
    asm("{ .reg .u64 t; cvta.to.shared.u64 t, %1; cvt.u32.u64 %0, t; }"
        : "=r"(r) : "l"(p));
    return r;
}
__device__ __forceinline__ void cpa16(uint32_t saddr, const void* gaddr) {
    asm volatile("cp.async.cg.shared.global [%0], [%1], 16;" :: "r"(saddr), "l"(gaddr));
}
__device__ __forceinline__ void cpa_commit() {
    asm volatile("cp.async.commit_group;" ::: "memory");
}
__device__ __forceinline__ void cpa_wait2() {
    asm volatile("cp.async.wait_group 2;" ::: "memory");
}
__device__ __forceinline__ void ldmatrix4(uint32_t* r, uint32_t addr) {
    asm volatile("ldmatrix.sync.aligned.m8n8.x4.shared.b16 {%0,%1,%2,%3}, [%4];"
                 : "=r"(r[0]), "=r"(r[1]), "=r"(r[2]), "=r"(r[3]) : "r"(addr));
}
__device__ __forceinline__ void mma16816(float* c, const uint32_t* a, uint32_t b0, uint32_t b1) {
    asm volatile(
        "mma.sync.aligned.m16n8k16.row.col.f32.bf16.bf16.f32 "
        "{%0,%1,%2,%3}, {%4,%5,%6,%7}, {%8,%9}, {%0,%1,%2,%3};"
        : "+f"(c[0]), "+f"(c[1]), "+f"(c[2]), "+f"(c[3])
        : "r"(a[0]), "r"(a[1]), "r"(a[2]), "r"(a[3]), "r"(b0), "r"(b1));
}

__global__ __launch_bounds__(256, 1)
void gemm_mma_kernel(const float* __restrict__ bias, float* __restrict__ C) {
    extern __shared__ __align__(16) char smem[];
    uint32_t sb = smem_u32(smem);
    int tid = threadIdx.x;
    int wid = tid >> 5, lid = tid & 31;
    int rowBase = blockIdx.x * 128;
    int colBase = blockIdx.y * 256;

    const __nv_bfloat16* srcs[4] = {
        g_a_hi + (size_t)rowBase * D_,
        g_a_lo + (size_t)rowBase * D_,
        g_bt_hi + (size_t)colBase * D_,
        g_bt_lo + (size_t)colBase * D_,
    };
    const uint32_t toff[4] = { 0, A_LO_O, B_HI_O, B_LO_O };
    const int trows[4] = { A_ROWS, A_ROWS, B_ROWS, B_ROWS };

    auto load_chunk = [&](int c, int s) {
        int k0 = c * 32;
        uint32_t stg = sb + (uint32_t)s * STG_SZ;
        #pragma unroll
        for (int t = 0; t < 4; t++) {
            const __nv_bfloat16* src = srcs[t] + k0;
            uint32_t base = stg + toff[t];
            int units = trows[t] * 4;                // 16B units (64B of K per row)
            for (int idx = tid; idx < units; idx += 256) {
                int r = idx >> 2, ch = idx & 3;
                cpa16(base + r * ROWB + ch * 16, src + (size_t)r * D_ + ch * 8);
            }
        }
    };

    load_chunk(0, 0); cpa_commit();
    load_chunk(1, 1); cpa_commit();

    int warpM = (wid & 1) * 64;       // 2 m-warps
    int warpN = (wid >> 1) * 64;      // 4 n-warps
    int lrow = lid & 15;
    int lk = (lid >> 4) * 8;

    float acc[4][8][4];
    #pragma unroll
    for (int i = 0; i < 4; i++)
        #pragma unroll
        for (int j = 0; j < 8; j++)
            #pragma unroll
            for (int v = 0; v < 4; v++) acc[i][j][v] = 0.f;

    #pragma unroll 1
    for (int c = 0; c < NCHUNK; c++) {
        if (c + 2 < NCHUNK) load_chunk(c + 2, (c + 2) % NSTAGE);
        cpa_commit();
        cpa_wait2();
        __syncthreads();

        uint32_t stg = sb + (uint32_t)(c % NSTAGE) * STG_SZ;
        #pragma unroll
        for (int term = 0; term < 3; term++) {
            uint32_t aoff = stg + (term == 1 ? A_LO_O : 0);
            uint32_t boff = stg + (term == 2 ? B_LO_O : B_HI_O);
            #pragma unroll
            for (int k16 = 0; k16 < 2; k16++) {
                uint32_t a[4][4];
                #pragma unroll
                for (int mi = 0; mi < 4; mi++)
                    ldmatrix4(a[mi], aoff + ((warpM + mi * 16 + lrow) * LDP + k16 * 16 + lk) * 2);
                uint32_t b[4][4];
                #pragma unroll
                for (int ni = 0; ni < 4; ni++)
                    ldmatrix4(b[ni], boff + ((warpN + ni * 16 + lrow) * LDP + k16 * 16 + lk) * 2);
                #pragma unroll
                for (int mi = 0; mi < 4; mi++)
                    #pragma unroll
                    for (int nj = 0; nj < 8; nj++) {
                        uint32_t b0 = (nj & 1) ? b[nj >> 1][1] : b[nj >> 1][0];
                        uint32_t b1 = (nj & 1) ? b[nj >> 1][3] : b[nj >> 1][2];
                        mma16816(acc[mi][nj], a[mi], b0, b1);
                    }
            }
        }
        __syncthreads();
    }

    // ---- epilogue: direct stores with bias ----
    int g = lid >> 2, tig = lid & 3;
    #pragma unroll
    for (int mi = 0; mi < 4; mi++) {
        #pragma unroll
        for (int nj = 0; nj < 8; nj++) {
            int row = rowBase + warpM + mi * 16 + g;
            int col = colBase + warpN + nj * 8 + tig * 2;
            float2 bv = *(const float2*)&bias[col];
            float2 o0 = { acc[mi][nj][0] + bv.x, acc[mi][nj][1] + bv.y };
            float2 o1 = { acc[mi][nj][2] + bv.x, acc[mi][nj][3] + bv.y };
            *(float2*)&C[(size_t)row * V_ + col] = o0;
            *(float2*)&C[(size_t)(row + 8) * V_ + col] = o1;
        }
    }
}

// ---------------- launch ----------------
extern "C" void kernel_launch(void* const* d_in, const int* in_sizes, int n_in,
                              void* d_out, int out_size) {
    const int*   x    = (const int*)d_in[0];
    const float* tab  = (const float*)d_in[1];
    const float* k1w  = (const float*)d_in[2];
    const float* k1b  = (const float*)d_in[3];
    const float* q1w  = (const float*)d_in[4];
    const float* q1b  = (const float*)d_in[5];
    const float* v1w  = (const float*)d_in[6];
    const float* v1b  = (const float*)d_in[7];
    const float* f1w  = (const float*)d_in[8];
    const float* f1b  = (const float*)d_in[9];
    const float* k2w  = (const float*)d_in[10];
    const float* k2b  = (const float*)d_in[11];
    const float* q2w  = (const float*)d_in[12];
    const float* q2b  = (const float*)d_in[13];
    const float* v2w  = (const float*)d_in[14];
    const float* v2b  = (const float*)d_in[15];
    const float* f2w  = (const float*)d_in[16];
    const float* f2b  = (const float*)d_in[17];
    const float* outw = (const float*)d_in[18];
    const float* outb = (const float*)d_in[19];
    float* out = (float*)d_out;

    cudaFuncSetAttribute(gemm_mma_kernel, cudaFuncAttributeMaxDynamicSharedMemorySize,
                         NSTAGE * STG_SZ);

    // out_w transpose+split is independent of everything upstream
    conv_b_kernel<<<dim3(V_ / 32, D_ / 32), dim3(32, 8)>>>(outw);

    embed_kernel<<<(R_ * D_) / 256, 256>>>(x, tab);

    // attention block 1: g_emb -> g_h1
    qkv_kernel<<<R_ / 8, 256>>>(0, k1w, k1b, q1w, q1b, v1w, v1b);
    scores_kernel<<<dim3(S_, B_), 256>>>();
    attv_kernel<<<dim3(16, KCH, 2), 128>>>();
    reduce_part_kernel<<<(R_ * HP) / 256, 256>>>();
    ff_kernel<<<(R_ * D_) / 256, 256>>>(0, f1w, f1b);

    // attention block 2: g_h1 -> bf16 split (fused in ff phase 1)
    qkv_kernel<<<R_ / 8, 256>>>(1, k2w, k2b, q2w, q2b, v2w, v2b);
    scores_kernel<<<dim3(S_, B_), 256>>>();
    attv_kernel<<<dim3(16, KCH, 2), 128>>>();
    reduce_part_kernel<<<(R_ * HP) / 256, 256>>>();
    ff_kernel<<<(R_ * D_) / 256, 256>>>(1, f2w, f2b);

    // final vocab projection on tensor cores (legacy HMMA path)
    gemm_mma_kernel<<<dim3(R_ / 128, V_ / 256), 256, NSTAGE * STG_SZ>>>(outb, out);
}

// round 7
// speedup vs baseline: 2.4936x; 1.1985x over previous
#include <cuda_runtime.h>
#include <cuda_bf16.h>
#include <cstdint>

#define B_ 2
#define S_ 2048
#define D_ 512
#define V_ 32000
#define H_ 11
#define HP 12           // padded H stride
#define R_ (B_*S_)      // 4096 rows
#define KCH 16          // attv k-chunks (128 keys each)

// GEMM tiling
#define LDP 40                          // padded row stride in bf16 halves (80 B)
#define ROWB (LDP * 2)                  // 80 bytes
#define TILE_A_BYTES (128 * ROWB)       // 10240
#define TILE_B_BYTES (256 * ROWB)       // 20480
#define NKC 16                          // K chunks of 32
#define MT_ (R_ / 128)                  // 32 row tiles
#define NT_ (V_ / 256)                  // 125 col tiles

// ---------------- scratch (device globals: allocation-free) ----------------
__device__ float g_emb[R_ * D_];
__device__ float g_h1 [R_ * D_];
__device__ float g_q  [R_ * HP];
__device__ float g_k  [R_ * HP];
__device__ float g_v  [R_ * HP];
__device__ float g_att[(size_t)B_ * S_ * S_];        // attT[b][k][q]
__device__ float g_part[KCH * R_ * HP];              // att@v partials
__device__ float g_res [R_ * HP];                    // summed partials
// pre-tiled, pre-padded bf16 operand images (byte-exact smem tiles)
__device__ uint4 g_a_hi4[(size_t)MT_ * NKC * TILE_A_BYTES / 16];
__device__ uint4 g_a_lo4[(size_t)MT_ * NKC * TILE_A_BYTES / 16];
__device__ uint4 g_bt_hi4[(size_t)NT_ * NKC * TILE_B_BYTES / 16];
__device__ uint4 g_bt_lo4[(size_t)NT_ * NKC * TILE_B_BYTES / 16];

// ---------------- 1) embedding + positional encoding ----------------
__global__ void embed_kernel(const int* __restrict__ x, const float* __restrict__ tab) {
    int idx = blockIdx.x * 256 + threadIdx.x;
    int d  = idx & (D_ - 1);
    int rs = idx >> 9;
    int s  = rs & (S_ - 1);
    int tok = x[rs];
    int e = d & ~1;
    float ang = (float)s * expf(-(float)e * (9.210340371976184f / 256.0f));
    float p = (d & 1) ? cosf(ang) : sinf(ang);
    g_emb[idx] = tab[(size_t)tok * D_ + d] + p;
}

// ---------------- 2) q/k/v projections ----------------
__global__ void qkv_kernel(int phase,
                           const float* __restrict__ kw, const float* __restrict__ kb,
                           const float* __restrict__ qw, const float* __restrict__ qb,
                           const float* __restrict__ vw, const float* __restrict__ vb) {
    const float* src = phase ? g_h1 : g_emb;
    __shared__ float Esh[8 * D_];
    int r0 = blockIdx.x * 8;
    int tid = threadIdx.x;
    for (int i = tid; i < 8 * D_; i += 256) Esh[i] = src[r0 * D_ + i];
    __syncthreads();
    for (int t = tid; t < 8 * 33; t += 256) {
        int row = t / 33, o = t % 33;
        const float *W, *bb; float* dst;
        if (o < 11)      { W = kw; bb = kb; dst = g_k; }
        else if (o < 22) { W = qw; bb = qb; dst = g_q; }
        else             { W = vw; bb = vb; dst = g_v; }
        int h = o % 11;
        float sacc = bb[h];
        const float* er = &Esh[row * D_];
        #pragma unroll 8
        for (int c = 0; c < D_; c++) sacc += er[c] * W[c * H_ + h];
        dst[(r0 + row) * HP + h] = sacc;
    }
}

// ---------------- 3) scores + causal mask + softmax over QUERY axis ----------------
__global__ void scores_kernel() {
    int k = blockIdx.x, b = blockIdx.y;
    int tid = threadIdx.x;
    __shared__ float kv[H_];
    __shared__ float red[256];
    if (tid < H_) kv[tid] = g_k[(b * S_ + k) * HP + tid];
    __syncthreads();

    float dloc[8];
    float m = -1e30f;
    int cnt = 0;
    for (int q = k + tid; q < S_; q += 256) {
        const float* qp = &g_q[(b * S_ + q) * HP];
        float d = 0.f;
        #pragma unroll
        for (int h = 0; h < H_; h++) d += qp[h] * kv[h];
        dloc[cnt++] = d;
        m = fmaxf(m, d);
    }
    red[tid] = m; __syncthreads();
    #pragma unroll
    for (int s = 128; s > 0; s >>= 1) {
        if (tid < s) red[tid] = fmaxf(red[tid], red[tid + s]);
        __syncthreads();
    }
    float M = red[0]; __syncthreads();

    float ssum = 0.f;
    for (int i = 0; i < cnt; i++) { dloc[i] = expf(dloc[i] - M); ssum += dloc[i]; }
    red[tid] = ssum; __syncthreads();
    #pragma unroll
    for (int s = 128; s > 0; s >>= 1) {
        if (tid < s) red[tid] += red[tid + s];
        __syncthreads();
    }
    float inv = 1.0f / red[0];

    size_t rowbase = ((size_t)b * S_ + k) * S_;
    cnt = 0;
    for (int q = k + tid; q < S_; q += 256) g_att[rowbase + q] = dloc[cnt++] * inv;
    for (int q = tid; q < k; q += 256)      g_att[rowbase + q] = 0.f;
}

// ---------------- 4) res = att @ v  (16 k-chunks, causal early-out) ----------------
__global__ void attv_kernel() {
    int qt = blockIdx.x, kc = blockIdx.y, b = blockIdx.z;
    int tid = threadIdx.x;
    int q = qt * 128 + tid;
    float* dst = &g_part[((kc * R_) + b * S_ + q) * HP];
    if (kc > qt) {                       // fully masked chunk
        #pragma unroll
        for (int h = 0; h < H_; h++) dst[h] = 0.f;
        return;
    }
    __shared__ float vsh[128 * HP];
    int k0 = kc * 128;
    const float* vbase = &g_v[(b * S_ + k0) * HP];
    for (int i = tid; i < 128 * HP; i += 128) vsh[i] = vbase[i];
    __syncthreads();

    float acc[H_];
    #pragma unroll
    for (int h = 0; h < H_; h++) acc[h] = 0.f;

    size_t attbase = ((size_t)b * S_ + k0) * S_ + q;
    for (int kk = 0; kk < 128; kk++) {
        float a = g_att[attbase + (size_t)kk * S_];
        const float* vr = &vsh[kk * HP];
        #pragma unroll
        for (int h = 0; h < H_; h++) acc[h] += a * vr[h];
    }
    #pragma unroll
    for (int h = 0; h < H_; h++) dst[h] = acc[h];
}

// ---------------- 4b) sum partials ----------------
__global__ void reduce_part_kernel() {
    int idx = blockIdx.x * 256 + threadIdx.x;        // [0, R_*HP)
    float s = 0.f;
    #pragma unroll
    for (int p = 0; p < KCH; p++) s += g_part[p * R_ * HP + idx];
    g_res[idx] = s;
}

// ---------------- 5) out = res @ fw + fb ----------------
// phase 0: fp32 to g_h1. phase 1: bf16 hi/lo split into tiled GEMM-A layout.
__global__ void ff_kernel(int phase, const float* __restrict__ fw, const float* __restrict__ fb) {
    int idx = blockIdx.x * 256 + threadIdx.x;
    int r = idx >> 9, d = idx & (D_ - 1);
    float sacc = fb[d];
    #pragma unroll
    for (int h = 0; h < H_; h++) sacc += g_res[r * HP + h] * fw[h * D_ + d];
    if (phase == 0) {
        g_h1[idx] = sacc;
    } else {
        __nv_bfloat16 hi = __float2bfloat16(sacc);
        __nv_bfloat16 lo = __float2bfloat16(sacc - __bfloat162float(hi));
        int mt = r >> 7, rrow = r & 127, kc = d >> 5, kk = d & 31;
        size_t off = (((size_t)(mt * NKC + kc) * 128) + rrow) * LDP + kk;
        ((__nv_bfloat16*)g_a_hi4)[off] = hi;
        ((__nv_bfloat16*)g_a_lo4)[off] = lo;
    }
}

// ---------------- 6a) transpose+split out_w -> tiled GEMM-B layout ----------------
__global__ void conv_b_kernel(const float* __restrict__ outw) {
    __shared__ float t[32][33];
    int v0 = blockIdx.x * 32, k0 = blockIdx.y * 32;
    int tx = threadIdx.x, ty = threadIdx.y;          // 32 x 8
    #pragma unroll
    for (int j = 0; j < 4; j++) {
        int k = k0 + ty + j * 8;
        t[ty + j * 8][tx] = outw[(size_t)k * V_ + v0 + tx];
    }
    __syncthreads();
    int kc = k0 >> 5;
    #pragma unroll
    for (int j = 0; j < 4; j++) {
        int v = v0 + ty + j * 8;
        float val = t[tx][ty + j * 8];               // = outw[k0+tx][v]
        __nv_bfloat16 hi = __float2bfloat16(val);
        __nv_bfloat16 lo = __float2bfloat16(val - __bfloat162float(hi));
        int nt = v >> 8, vrow = v & 255;
        size_t off = (((size_t)(nt * NKC + kc) * 256) + vrow) * LDP + tx;
        ((__nv_bfloat16*)g_bt_hi4)[off] = hi;
        ((__nv_bfloat16*)g_bt_lo4)[off] = lo;
    }
}

// ---------------- 6b) bulk-copy pipelined split-bf16 MMA GEMM ----------------
// Tile 128x256, K-chunk 32, 3-stage cp.async.bulk + mbarrier pipeline.
#define A_LO_O TILE_A_BYTES                  // 10240
#define B_HI_O (2 * TILE_A_BYTES)            // 20480
#define B_LO_O (B_HI_O + TILE_B_BYTES)       // 40960
#define STG_SZ (B_HI_O + 2 * TILE_B_BYTES)   // 61440
#define NSTAGE 3
#define CTRL 1024
#define GSMEM (CTRL + NSTAGE * STG_SZ)

__device__ __forceinline__ uint32_t smem_u32(const void* p) {
    uint32_t r;
    asm("{ .reg .u64 t; cvta.to.shared.u64 t, %1; cvt.u32.u64 %0, t; }"
        : "=r"(r) : "l"(p));
    return r;
}
__device__ __forceinline__ void bulk_g2s(uint32_t dst, const void* src, uint32_t bytes,
                                         uint32_t mbar) {
    asm volatile(
        "cp.async.bulk.shared::cluster.global.mbarrier::complete_tx::bytes [%0], [%1], %2, [%3];"
        :: "r"(dst), "l"(src), "r"(bytes), "r"(mbar) : "memory");
}
__device__ __forceinline__ void mbar_expect(uint32_t mbar, uint32_t bytes) {
    asm volatile("mbarrier.arrive.expect_tx.shared.b64 _, [%0], %1;"
                 :: "r"(mbar), "r"(bytes) : "memory");
}
__device__ __forceinline__ void mbar_wait(uint32_t addr, uint32_t parity) {
    asm volatile(
        "{\n\t.reg .pred P;\n\t"
        "W_%=:\n\t"
        "mbarrier.try_wait.parity.acquire.cta.shared::cta.b64 P, [%0], %1, 0x989680;\n\t"
        "@P bra.uni D_%=;\n\t"
        "bra.uni W_%=;\n\t"
        "D_%=:\n\t}"
        :: "r"(addr), "r"(parity) : "memory");
}
__device__ __forceinline__ void ldmatrix4(uint32_t* r, uint32_t addr) {
    asm volatile("ldmatrix.sync.aligned.m8n8.x4.shared.b16 {%0,%1,%2,%3}, [%4];"
                 : "=r"(r[0]), "=r"(r[1]), "=r"(r[2]), "=r"(r[3]) : "r"(addr));
}
__device__ __forceinline__ void mma16816(float* c, const uint32_t* a, uint32_t b0, uint32_t b1) {
    asm volatile(
        "mma.sync.aligned.m16n8k16.row.col.f32.bf16.bf16.f32 "
        "{%0,%1,%2,%3}, {%4,%5,%6,%7}, {%8,%9}, {%0,%1,%2,%3};"
        : "+f"(c[0]), "+f"(c[1]), "+f"(c[2]), "+f"(c[3])
        : "r"(a[0]), "r"(a[1]), "r"(a[2]), "r"(a[3]), "r"(b0), "r"(b1));
}

__global__ __launch_bounds__(256, 1)
void gemm_mma_kernel(const float* __restrict__ bias, float* __restrict__ C) {
    extern __shared__ __align__(16) char smem[];
    uint32_t sb = smem_u32(smem);
    int tid = threadIdx.x;
    int wid = tid >> 5, lid = tid & 31;
    int rowBase = blockIdx.x * 128;
    int colBase = blockIdx.y * 256;

    const char* gAh = (const char*)g_a_hi4 + (size_t)blockIdx.x * NKC * TILE_A_BYTES;
    const char* gAl = (const char*)g_a_lo4 + (size_t)blockIdx.x * NKC * TILE_A_BYTES;
    const char* gBh = (const char*)g_bt_hi4 + (size_t)blockIdx.y * NKC * TILE_B_BYTES;
    const char* gBl = (const char*)g_bt_lo4 + (size_t)blockIdx.y * NKC * TILE_B_BYTES;

    if (tid == 0) {
        #pragma unroll
        for (int s = 0; s < NSTAGE; s++)
            asm volatile("mbarrier.init.shared.b64 [%0], 1;" :: "r"(sb + 8u * s) : "memory");
    }
    __syncthreads();

    auto issue = [&](int c, int s) {
        uint32_t mb = sb + 8u * s;
        uint32_t stg = sb + CTRL + (uint32_t)s * STG_SZ;
        mbar_expect(mb, STG_SZ);
        bulk_g2s(stg,          gAh + (size_t)c * TILE_A_BYTES, TILE_A_BYTES, mb);
        bulk_g2s(stg + A_LO_O, gAl + (size_t)c * TILE_A_BYTES, TILE_A_BYTES, mb);
        bulk_g2s(stg + B_HI_O,                 gBh + (size_t)c * TILE_B_BYTES, TILE_B_BYTES / 2, mb);
        bulk_g2s(stg + B_HI_O + TILE_B_BYTES / 2, gBh + (size_t)c * TILE_B_BYTES + TILE_B_BYTES / 2, TILE_B_BYTES / 2, mb);
        bulk_g2s(stg + B_LO_O,                 gBl + (size_t)c * TILE_B_BYTES, TILE_B_BYTES / 2, mb);
        bulk_g2s(stg + B_LO_O + TILE_B_BYTES / 2, gBl + (size_t)c * TILE_B_BYTES + TILE_B_BYTES / 2, TILE_B_BYTES / 2, mb);
    };

    if (tid == 0) { issue(0, 0); issue(1, 1); issue(2, 2); }

    int warpM = (wid & 1) * 64;       // 2 m-warps
    int warpN = (wid >> 1) * 64;      // 4 n-warps
    int lrow = lid & 15;
    int lk = (lid >> 4) * 8;

    float acc[4][8][4];
    #pragma unroll
    for (int i = 0; i < 4; i++)
        #pragma unroll
        for (int j = 0; j < 8; j++)
            #pragma unroll
            for (int v = 0; v < 4; v++) acc[i][j][v] = 0.f;

    #pragma unroll 1
    for (int c = 0; c < NKC; c++) {
        int s = c % NSTAGE;
        mbar_wait(sb + 8u * s, (c / NSTAGE) & 1);
        uint32_t stg = sb + CTRL + (uint32_t)s * STG_SZ;

        #pragma unroll
        for (int term = 0; term < 3; term++) {
            uint32_t aoff = stg + (term == 1 ? A_LO_O : 0);
            uint32_t boff = stg + (term == 2 ? B_LO_O : B_HI_O);
            #pragma unroll
            for (int k16 = 0; k16 < 2; k16++) {
                uint32_t a[4][4];
                #pragma unroll
                for (int mi = 0; mi < 4; mi++)
                    ldmatrix4(a[mi], aoff + ((warpM + mi * 16 + lrow) * LDP + k16 * 16 + lk) * 2);
                uint32_t b[4][4];
                #pragma unroll
                for (int ni = 0; ni < 4; ni++)
                    ldmatrix4(b[ni], boff + ((warpN + ni * 16 + lrow) * LDP + k16 * 16 + lk) * 2);
                #pragma unroll
                for (int mi = 0; mi < 4; mi++)
                    #pragma unroll
                    for (int nj = 0; nj < 8; nj++) {
                        uint32_t b0 = (nj & 1) ? b[nj >> 1][1] : b[nj >> 1][0];
                        uint32_t b1 = (nj & 1) ? b[nj >> 1][3] : b[nj >> 1][2];
                        mma16816(acc[mi][nj], a[mi], b0, b1);
                    }
            }
        }
        __syncthreads();
        if (tid == 0 && c + NSTAGE < NKC) issue(c + NSTAGE, s);
    }

    // ---- epilogue: direct stores with bias ----
    int g = lid >> 2, tig = lid & 3;
    #pragma unroll
    for (int mi = 0; mi < 4; mi++) {
        #pragma unroll
        for (int nj = 0; nj < 8; nj++) {
            int row = rowBase + warpM + mi * 16 + g;
            int col = colBase + warpN + nj * 8 + tig * 2;
            float2 bv = *(const float2*)&bias[col];
            float2 o0 = { acc[mi][nj][0] + bv.x, acc[mi][nj][1] + bv.y };
            float2 o1 = { acc[mi][nj][2] + bv.x, acc[mi][nj][3] + bv.y };
            *(float2*)&C[(size_t)row * V_ + col] = o0;
            *(float2*)&C[(size_t)(row + 8) * V_ + col] = o1;
        }
    }
}

// ---------------- launch ----------------
extern "C" void kernel_launch(void* const* d_in, const int* in_sizes, int n_in,
                              void* d_out, int out_size) {
    const int*   x    = (const int*)d_in[0];
    const float* tab  = (const float*)d_in[1];
    const float* k1w  = (const float*)d_in[2];
    const float* k1b  = (const float*)d_in[3];
    const float* q1w  = (const float*)d_in[4];
    const float* q1b  = (const float*)d_in[5];
    const float* v1w  = (const float*)d_in[6];
    const float* v1b  = (const float*)d_in[7];
    const float* f1w  = (const float*)d_in[8];
    const float* f1b  = (const float*)d_in[9];
    const float* k2w  = (const float*)d_in[10];
    const float* k2b  = (const float*)d_in[11];
    const float* q2w  = (const float*)d_in[12];
    const float* q2b  = (const float*)d_in[13];
    const float* v2w  = (const float*)d_in[14];
    const float* v2b  = (const float*)d_in[15];
    const float* f2w  = (const float*)d_in[16];
    const float* f2b  = (const float*)d_in[17];
    const float* outw = (const float*)d_in[18];
    const float* outb = (const float*)d_in[19];
    float* out = (float*)d_out;

    cudaFuncSetAttribute(gemm_mma_kernel, cudaFuncAttributeMaxDynamicSharedMemorySize, GSMEM);

    // out_w transpose+split is independent of everything upstream
    conv_b_kernel<<<dim3(V_ / 32, D_ / 32), dim3(32, 8)>>>(outw);

    embed_kernel<<<(R_ * D_) / 256, 256>>>(x, tab);

    // attention block 1: g_emb -> g_h1
    qkv_kernel<<<R_ / 8, 256>>>(0, k1w, k1b, q1w, q1b, v1w, v1b);
    scores_kernel<<<dim3(S_, B_), 256>>>();
    attv_kernel<<<dim3(16, KCH, 2), 128>>>();
    reduce_part_kernel<<<(R_ * HP) / 256, 256>>>();
    ff_kernel<<<(R_ * D_) / 256, 256>>>(0, f1w, f1b);

    // attention block 2: g_h1 -> tiled bf16 split (fused in ff phase 1)
    qkv_kernel<<<R_ / 8, 256>>>(1, k2w, k2b, q2w, q2b, v2w, v2b);
    scores_kernel<<<dim3(S_, B_), 256>>>();
    attv_kernel<<<dim3(16, KCH, 2), 128>>>();
    reduce_part_kernel<<<(R_ * HP) / 256, 256>>>();
    ff_kernel<<<(R_ * D_) / 256, 256>>>(1, f2w, f2b);

    // final vocab projection: bulk-fed tensor-core GEMM
    gemm_mma_kernel<<<dim3(MT_, NT_), 256, GSMEM>>>(outb, out);
}

// round 8
// speedup vs baseline: 3.2504x; 1.3035x over previous
#include <cuda_runtime.h>
#include <cuda_fp16.h>
#include <cstdint>

#define B_ 2
#define S_ 2048
#define D_ 512
#define V_ 32000
#define H_ 11
#define HP 12           // padded H stride
#define R_ (B_*S_)      // 4096 rows
#define KCH 16          // attv k-chunks (128 keys each)

// GEMM tiling
#define LDP 40                          // padded row stride in fp16 halves (80 B)
#define ROWB (LDP * 2)                  // 80 bytes
#define TILE_A_BYTES (128 * ROWB)       // 10240
#define TILE_B_BYTES (256 * ROWB)       // 20480
#define NKC 16                          // K chunks of 32
#define MT_ (R_ / 128)                  // 32 row tiles
#define NT_ (V_ / 256)                  // 125 col tiles

// split-precision scaling (exact powers of 2)
#define A_SCALE 16.0f                   // 2^4
#define B_SCALE 64.0f                   // 2^6
#define OUT_SCALE (1.0f / 1024.0f)      // 2^-10

// ---------------- scratch (device globals: allocation-free) ----------------
__device__ float g_emb[R_ * D_];
__device__ float g_h1 [R_ * D_];
__device__ float g_q  [R_ * HP];
__device__ float g_k  [R_ * HP];
__device__ float g_v  [R_ * HP];
__device__ float g_att[(size_t)B_ * S_ * S_];        // attT[b][k][q]
__device__ float g_part[KCH * R_ * HP];              // att@v partials
__device__ float g_res [R_ * HP];                    // summed partials
// pre-tiled, pre-padded fp16 operand images (byte-exact smem tiles)
__device__ uint4 g_a_hi4[(size_t)MT_ * NKC * TILE_A_BYTES / 16];
__device__ uint4 g_a_lo4[(size_t)MT_ * NKC * TILE_A_BYTES / 16];
__device__ uint4 g_bt_hi4[(size_t)NT_ * NKC * TILE_B_BYTES / 16];

// ---------------- 1) embedding + positional encoding ----------------
__global__ void embed_kernel(const int* __restrict__ x, const float* __restrict__ tab) {
    int idx = blockIdx.x * 256 + threadIdx.x;
    int d  = idx & (D_ - 1);
    int rs = idx >> 9;
    int s  = rs & (S_ - 1);
    int tok = x[rs];
    int e = d & ~1;
    float ang = (float)s * expf(-(float)e * (9.210340371976184f / 256.0f));
    float p = (d & 1) ? cosf(ang) : sinf(ang);
    g_emb[idx] = tab[(size_t)tok * D_ + d] + p;
}

// ---------------- 2) q/k/v projections ----------------
__global__ void qkv_kernel(int phase,
                           const float* __restrict__ kw, const float* __restrict__ kb,
                           const float* __restrict__ qw, const float* __restrict__ qb,
                           const float* __restrict__ vw, const float* __restrict__ vb) {
    const float* src = phase ? g_h1 : g_emb;
    __shared__ float Esh[8 * D_];
    int r0 = blockIdx.x * 8;
    int tid = threadIdx.x;
    for (int i = tid; i < 8 * D_; i += 256) Esh[i] = src[r0 * D_ + i];
    __syncthreads();
    for (int t = tid; t < 8 * 33; t += 256) {
        int row = t / 33, o = t % 33;
        const float *W, *bb; float* dst;
        if (o < 11)      { W = kw; bb = kb; dst = g_k; }
        else if (o < 22) { W = qw; bb = qb; dst = g_q; }
        else             { W = vw; bb = vb; dst = g_v; }
        int h = o % 11;
        float sacc = bb[h];
        const float* er = &Esh[row * D_];
        #pragma unroll 8
        for (int c = 0; c < D_; c++) sacc += er[c] * W[c * H_ + h];
        dst[(r0 + row) * HP + h] = sacc;
    }
}

// ---------------- 3) scores + causal mask + softmax over QUERY axis ----------------
__global__ void scores_kernel() {
    int k = blockIdx.x, b = blockIdx.y;
    int tid = threadIdx.x;
    __shared__ float kv[H_];
    __shared__ float red[256];
    if (tid < H_) kv[tid] = g_k[(b * S_ + k) * HP + tid];
    __syncthreads();

    float dloc[8];
    float m = -1e30f;
    int cnt = 0;
    for (int q = k + tid; q < S_; q += 256) {
        const float* qp = &g_q[(b * S_ + q) * HP];
        float d = 0.f;
        #pragma unroll
        for (int h = 0; h < H_; h++) d += qp[h] * kv[h];
        dloc[cnt++] = d;
        m = fmaxf(m, d);
    }
    red[tid] = m; __syncthreads();
    #pragma unroll
    for (int s = 128; s > 0; s >>= 1) {
        if (tid < s) red[tid] = fmaxf(red[tid], red[tid + s]);
        __syncthreads();
    }
    float M = red[0]; __syncthreads();

    float ssum = 0.f;
    for (int i = 0; i < cnt; i++) { dloc[i] = expf(dloc[i] - M); ssum += dloc[i]; }
    red[tid] = ssum; __syncthreads();
    #pragma unroll
    for (int s = 128; s > 0; s >>= 1) {
        if (tid < s) red[tid] += red[tid + s];
        __syncthreads();
    }
    float inv = 1.0f / red[0];

    size_t rowbase = ((size_t)b * S_ + k) * S_;
    cnt = 0;
    for (int q = k + tid; q < S_; q += 256) g_att[rowbase + q] = dloc[cnt++] * inv;
    for (int q = tid; q < k; q += 256)      g_att[rowbase + q] = 0.f;
}

// ---------------- 4) res = att @ v  (16 k-chunks, causal early-out) ----------------
__global__ void attv_kernel() {
    int qt = blockIdx.x, kc = blockIdx.y, b = blockIdx.z;
    int tid = threadIdx.x;
    int q = qt * 128 + tid;
    float* dst = &g_part[((kc * R_) + b * S_ + q) * HP];
    if (kc > qt) {                       // fully masked chunk
        #pragma unroll
        for (int h = 0; h < H_; h++) dst[h] = 0.f;
        return;
    }
    __shared__ float vsh[128 * HP];
    int k0 = kc * 128;
    const float* vbase = &g_v[(b * S_ + k0) * HP];
    for (int i = tid; i < 128 * HP; i += 128) vsh[i] = vbase[i];
    __syncthreads();

    float acc[H_];
    #pragma unroll
    for (int h = 0; h < H_; h++) acc[h] = 0.f;

    size_t attbase = ((size_t)b * S_ + k0) * S_ + q;
    for (int kk = 0; kk < 128; kk++) {
        float a = g_att[attbase + (size_t)kk * S_];
        const float* vr = &vsh[kk * HP];
        #pragma unroll
        for (int h = 0; h < H_; h++) acc[h] += a * vr[h];
    }
    #pragma unroll
    for (int h = 0; h < H_; h++) dst[h] = acc[h];
}

// ---------------- 4b) sum partials ----------------
__global__ void reduce_part_kernel() {
    int idx = blockIdx.x * 256 + threadIdx.x;        // [0, R_*HP)
    float s = 0.f;
    #pragma unroll
    for (int p = 0; p < KCH; p++) s += g_part[p * R_ * HP + idx];
    g_res[idx] = s;
}

// ---------------- 5) out = res @ fw + fb ----------------
// phase 0: fp32 to g_h1. phase 1: fp16 hi/lo split (x A_SCALE) into tiled GEMM-A layout.
__global__ void ff_kernel(int phase, const float* __restrict__ fw, const float* __restrict__ fb) {
    int idx = blockIdx.x * 256 + threadIdx.x;
    int r = idx >> 9, d = idx & (D_ - 1);
    float sacc = fb[d];
    #pragma unroll
    for (int h = 0; h < H_; h++) sacc += g_res[r * HP + h] * fw[h * D_ + d];
    if (phase == 0) {
        g_h1[idx] = sacc;
    } else {
        float a = sacc * A_SCALE;
        __half hi = __float2half(a);
        __half lo = __float2half(a - __half2float(hi));
        int mt = r >> 7, rrow = r & 127, kc = d >> 5, kk = d & 31;
        size_t off = (((size_t)(mt * NKC + kc) * 128) + rrow) * LDP + kk;
        ((__half*)g_a_hi4)[off] = hi;
        ((__half*)g_a_lo4)[off] = lo;
    }
}

// ---------------- 6a) transpose out_w -> tiled fp16 GEMM-B layout (hi only) ---------
__global__ void conv_b_kernel(const float* __restrict__ outw) {
    __shared__ float t[32][33];
    int v0 = blockIdx.x * 32, k0 = blockIdx.y * 32;
    int tx = threadIdx.x, ty = threadIdx.y;          // 32 x 8
    #pragma unroll
    for (int j = 0; j < 4; j++) {
        int k = k0 + ty + j * 8;
        t[ty + j * 8][tx] = outw[(size_t)k * V_ + v0 + tx];
    }
    __syncthreads();
    int kc = k0 >> 5;
    #pragma unroll
    for (int j = 0; j < 4; j++) {
        int v = v0 + ty + j * 8;
        float val = t[tx][ty + j * 8] * B_SCALE;     // = outw[k0+tx][v] * 2^6
        int nt = v >> 8, vrow = v & 255;
        size_t off = (((size_t)(nt * NKC + kc) * 256) + vrow) * LDP + tx;
        ((__half*)g_bt_hi4)[off] = __float2half(val);
    }
}

// ---------------- 6b) bulk-copy pipelined 2-term fp16 MMA GEMM ----------------
// Tile 128x256, K-chunk 32, 4-stage cp.async.bulk + mbarrier pipeline.
// C = (Ah*Bh + Al*Bh) * 2^-10 + bias;  dropped A*Bl ~ 2.8e-4 relative.
#define A_LO_O TILE_A_BYTES                  // 10240
#define B_HI_O (2 * TILE_A_BYTES)            // 20480
#define STG_SZ (B_HI_O + TILE_B_BYTES)       // 40960
#define NSTAGE 4
#define CTRL 1024
#define GSMEM (CTRL + NSTAGE * STG_SZ)       // 164864

__device__ __forceinline__ uint32_t smem_u32(const void* p) {
    uint32_t r;
    asm("{ .reg .u64 t; cvta.to.shared.u64 t, %1; cvt.u32.u64 %0, t; }"
        : "=r"(r) : "l"(p));
    return r;
}
__device__ __forceinline__ void bulk_g2s(uint32_t dst, const void* src, uint32_t bytes,
                                         uint32_t mbar) {
    asm volatile(
        "cp.async.bulk.shared::cluster.global.mbarrier::complete_tx::bytes [%0], [%1], %2, [%3];"
        :: "r"(dst), "l"(src), "r"(bytes), "r"(mbar) : "memory");
}
__device__ __forceinline__ void mbar_expect(uint32_t mbar, uint32_t bytes) {
    asm volatile("mbarrier.arrive.expect_tx.shared.b64 _, [%0], %1;"
                 :: "r"(mbar), "r"(bytes) : "memory");
}
__device__ __forceinline__ void mbar_wait(uint32_t addr, uint32_t parity) {
    asm volatile(
        "{\n\t.reg .pred P;\n\t"
        "W_%=:\n\t"
        "mbarrier.try_wait.parity.acquire.cta.shared::cta.b64 P, [%0], %1, 0x989680;\n\t"
        "@P bra.uni D_%=;\n\t"
        "bra.uni W_%=;\n\t"
        "D_%=:\n\t}"
        :: "r"(addr), "r"(parity) : "memory");
}
__device__ __forceinline__ void ldmatrix4(uint32_t* r, uint32_t addr) {
    asm volatile("ldmatrix.sync.aligned.m8n8.x4.shared.b16 {%0,%1,%2,%3}, [%4];"
                 : "=r"(r[0]), "=r"(r[1]), "=r"(r[2]), "=r"(r[3]) : "r"(addr));
}
__device__ __forceinline__ void mma16816(float* c, const uint32_t* a, uint32_t b0, uint32_t b1) {
    asm volatile(
        "mma.sync.aligned.m16n8k16.row.col.f32.f16.f16.f32 "
        "{%0,%1,%2,%3}, {%4,%5,%6,%7}, {%8,%9}, {%0,%1,%2,%3};"
        : "+f"(c[0]), "+f"(c[1]), "+f"(c[2]), "+f"(c[3])
        : "r"(a[0]), "r"(a[1]), "r"(a[2]), "r"(a[3]), "r"(b0), "r"(b1));
}

__global__ __launch_bounds__(256, 1)
void gemm_mma_kernel(const float* __restrict__ bias, float* __restrict__ C) {
    extern __shared__ __align__(16) char smem[];
    uint32_t sb = smem_u32(smem);
    int tid = threadIdx.x;
    int wid = tid >> 5, lid = tid & 31;
    int rowBase = blockIdx.x * 128;
    int colBase = blockIdx.y * 256;

    const char* gAh = (const char*)g_a_hi4 + (size_t)blockIdx.x * NKC * TILE_A_BYTES;
    const char* gAl = (const char*)g_a_lo4 + (size_t)blockIdx.x * NKC * TILE_A_BYTES;
    const char* gBh = (const char*)g_bt_hi4 + (size_t)blockIdx.y * NKC * TILE_B_BYTES;

    if (tid == 0) {
        #pragma unroll
        for (int s = 0; s < NSTAGE; s++)
            asm volatile("mbarrier.init.shared.b64 [%0], 1;" :: "r"(sb + 8u * s) : "memory");
    }
    __syncthreads();

    auto issue = [&](int c, int s) {
        uint32_t mb = sb + 8u * s;
        uint32_t stg = sb + CTRL + (uint32_t)s * STG_SZ;
        mbar_expect(mb, STG_SZ);
        bulk_g2s(stg,          gAh + (size_t)c * TILE_A_BYTES, TILE_A_BYTES, mb);
        bulk_g2s(stg + A_LO_O, gAl + (size_t)c * TILE_A_BYTES, TILE_A_BYTES, mb);
        bulk_g2s(stg + B_HI_O,                    gBh + (size_t)c * TILE_B_BYTES, TILE_B_BYTES / 2, mb);
        bulk_g2s(stg + B_HI_O + TILE_B_BYTES / 2, gBh + (size_t)c * TILE_B_BYTES + TILE_B_BYTES / 2, TILE_B_BYTES / 2, mb);
    };

    if (tid == 0) { issue(0, 0); issue(1, 1); issue(2, 2); issue(3, 3); }

    int warpM = (wid & 1) * 64;       // 2 m-warps
    int warpN = (wid >> 1) * 64;      // 4 n-warps
    int lrow = lid & 15;
    int lk = (lid >> 4) * 8;

    float acc[4][8][4];
    #pragma unroll
    for (int i = 0; i < 4; i++)
        #pragma unroll
        for (int j = 0; j < 8; j++)
            #pragma unroll
            for (int v = 0; v < 4; v++) acc[i][j][v] = 0.f;

    #pragma unroll 1
    for (int c = 0; c < NKC; c++) {
        int s = c % NSTAGE;
        mbar_wait(sb + 8u * s, (c / NSTAGE) & 1);
        uint32_t stg = sb + CTRL + (uint32_t)s * STG_SZ;

        #pragma unroll
        for (int term = 0; term < 2; term++) {
            uint32_t aoff = stg + (term ? A_LO_O : 0);
            uint32_t boff = stg + B_HI_O;
            #pragma unroll
            for (int k16 = 0; k16 < 2; k16++) {
                uint32_t a[4][4];
                #pragma unroll
                for (int mi = 0; mi < 4; mi++)
                    ldmatrix4(a[mi], aoff + ((warpM + mi * 16 + lrow) * LDP + k16 * 16 + lk) * 2);
                uint32_t b[4][4];
                #pragma unroll
                for (int ni = 0; ni < 4; ni++)
                    ldmatrix4(b[ni], boff + ((warpN + ni * 16 + lrow) * LDP + k16 * 16 + lk) * 2);
                #pragma unroll
                for (int mi = 0; mi < 4; mi++)
                    #pragma unroll
                    for (int nj = 0; nj < 8; nj++) {
                        uint32_t b0 = (nj & 1) ? b[nj >> 1][1] : b[nj >> 1][0];
                        uint32_t b1 = (nj & 1) ? b[nj >> 1][3] : b[nj >> 1][2];
                        mma16816(acc[mi][nj], a[mi], b0, b1);
                    }
            }
        }
        __syncthreads();
        if (tid == 0 && c + NSTAGE < NKC) issue(c + NSTAGE, s);
    }

    // ---- epilogue: unscale + bias, direct stores ----
    int g = lid >> 2, tig = lid & 3;
    #pragma unroll
    for (int mi = 0; mi < 4; mi++) {
        #pragma unroll
        for (int nj = 0; nj < 8; nj++) {
            int row = rowBase + warpM + mi * 16 + g;
            int col = colBase + warpN + nj * 8 + tig * 2;
            float2 bv = *(const float2*)&bias[col];
            float2 o0 = { acc[mi][nj][0] * OUT_SCALE + bv.x, acc[mi][nj][1] * OUT_SCALE + bv.y };
            float2 o1 = { acc[mi][nj][2] * OUT_SCALE + bv.x, acc[mi][nj][3] * OUT_SCALE + bv.y };
            *(float2*)&C[(size_t)row * V_ + col] = o0;
            *(float2*)&C[(size_t)(row + 8) * V_ + col] = o1;
        }
    }
}

// ---------------- launch ----------------
extern "C" void kernel_launch(void* const* d_in, const int* in_sizes, int n_in,
                              void* d_out, int out_size) {
    const int*   x    = (const int*)d_in[0];
    const float* tab  = (const float*)d_in[1];
    const float* k1w  = (const float*)d_in[2];
    const float* k1b  = (const float*)d_in[3];
    const float* q1w  = (const float*)d_in[4];
    const float* q1b  = (const float*)d_in[5];
    const float* v1w  = (const float*)d_in[6];
    const float* v1b  = (const float*)d_in[7];
    const float* f1w  = (const float*)d_in[8];
    const float* f1b  = (const float*)d_in[9];
    const float* k2w  = (const float*)d_in[10];
    const float* k2b  = (const float*)d_in[11];
    const float* q2w  = (const float*)d_in[12];
    const float* q2b  = (const float*)d_in[13];
    const float* v2w  = (const float*)d_in[14];
    const float* v2b  = (const float*)d_in[15];
    const float* f2w  = (const float*)d_in[16];
    const float* f2b  = (const float*)d_in[17];
    const float* outw = (const float*)d_in[18];
    const float* outb = (const float*)d_in[19];
    float* out = (float*)d_out;

    cudaFuncSetAttribute(gemm_mma_kernel, cudaFuncAttributeMaxDynamicSharedMemorySize, GSMEM);

    // out_w transpose (fp16, scaled) is independent of everything upstream
    conv_b_kernel<<<dim3(V_ / 32, D_ / 32), dim3(32, 8)>>>(outw);

    embed_kernel<<<(R_ * D_) / 256, 256>>>(x, tab);

    // attention block 1: g_emb -> g_h1
    qkv_kernel<<<R_ / 8, 256>>>(0, k1w, k1b, q1w, q1b, v1w, v1b);
    scores_kernel<<<dim3(S_, B_), 256>>>();
    attv_kernel<<<dim3(16, KCH, 2), 128>>>();
    reduce_part_kernel<<<(R_ * HP) / 256, 256>>>();
    ff_kernel<<<(R_ * D_) / 256, 256>>>(0, f1w, f1b);

    // attention block 2: g_h1 -> tiled fp16 split (fused in ff phase 1)
    qkv_kernel<<<R_ / 8, 256>>>(1, k2w, k2b, q2w, q2b, v2w, v2b);
    scores_kernel<<<dim3(S_, B_), 256>>>();
    attv_kernel<<<dim3(16, KCH, 2), 128>>>();
    reduce_part_kernel<<<(R_ * HP) / 256, 256>>>();
    ff_kernel<<<(R_ * D_) / 256, 256>>>(1, f2w, f2b);

    // final vocab projection: bulk-fed 2-term fp16 tensor-core GEMM
    gemm_mma_kernel<<<dim3(MT_, NT_), 256, GSMEM>>>(outb, out);
}

// round 11
// speedup vs baseline: 4.6313x; 1.4249x over previous
#include <cuda_runtime.h>
#include <cuda_fp16.h>
#include <cstdint>

#define B_ 2
#define S_ 2048
#define D_ 512
#define V_ 32000
#define H_ 11
#define HP 12           // padded H stride
#define R_ (B_*S_)      // 4096 rows
#define KCH 16          // attv k-chunks (128 keys each)

// GEMM tiling
#define LDP 40                          // padded row stride in fp16 halves (80 B)
#define ROWB (LDP * 2)                  // 80 bytes
#define TILE_A_BYTES (128 * ROWB)       // 10240
#define TILE_B_BYTES (256 * ROWB)       // 20480
#define NKC 16                          // K chunks of 32
#define MT_ (R_ / 128)                  // 32 row tiles
#define NT_ (V_ / 256)                  // 125 col tiles

// fp16 scaling (exact powers of 2)
#define A_SCALE 16.0f                   // 2^4
#define B_SCALE 64.0f                   // 2^6
#define OUT_SCALE (1.0f / 1024.0f)      // 2^-10

// ---------------- scratch (device globals: allocation-free) ----------------
__device__ float g_emb[R_ * D_];
__device__ float g_h1 [R_ * D_];
__device__ float g_q  [R_ * HP];
__device__ float g_k  [R_ * HP];
__device__ float g_v  [R_ * HP];
__device__ float g_att[(size_t)B_ * S_ * S_];        // attT[b][k][q]
__device__ float g_part[KCH * R_ * HP];              // att@v partials
__device__ float g_res [R_ * HP];                    // summed partials
// pre-tiled, pre-padded fp16 operand images (byte-exact smem tiles)
__device__ uint4 g_a_hi4[(size_t)MT_ * NKC * TILE_A_BYTES / 16];
__device__ uint4 g_bt_hi4[(size_t)NT_ * NKC * TILE_B_BYTES / 16];

// ---------------- 1) embedding + positional encoding ----------------
__global__ void embed_kernel(const int* __restrict__ x, const float* __restrict__ tab) {
    int idx = blockIdx.x * 256 + threadIdx.x;
    int d  = idx & (D_ - 1);
    int rs = idx >> 9;
    int s  = rs & (S_ - 1);
    int tok = x[rs];
    int e = d & ~1;
    float ang = (float)s * expf(-(float)e * (9.210340371976184f / 256.0f));
    float p = (d & 1) ? cosf(ang) : sinf(ang);
    g_emb[idx] = tab[(size_t)tok * D_ + d] + p;
}

// ---------------- 2) q/k/v projections ----------------
__global__ void qkv_kernel(int phase,
                           const float* __restrict__ kw, const float* __restrict__ kb,
                           const float* __restrict__ qw, const float* __restrict__ qb,
                           const float* __restrict__ vw, const float* __restrict__ vb) {
    const float* src = phase ? g_h1 : g_emb;
    __shared__ float Esh[8 * D_];
    int r0 = blockIdx.x * 8;
    int tid = threadIdx.x;
    for (int i = tid; i < 8 * D_; i += 256) Esh[i] = src[r0 * D_ + i];
    __syncthreads();
    for (int t = tid; t < 8 * 33; t += 256) {
        int row = t / 33, o = t % 33;
        const float *W, *bb; float* dst;
        if (o < 11)      { W = kw; bb = kb; dst = g_k; }
        else if (o < 22) { W = qw; bb = qb; dst = g_q; }
        else             { W = vw; bb = vb; dst = g_v; }
        int h = o % 11;
        float sacc = bb[h];
        const float* er = &Esh[row * D_];
        #pragma unroll 8
        for (int c = 0; c < D_; c++) sacc += er[c] * W[c * H_ + h];
        dst[(r0 + row) * HP + h] = sacc;
    }
}

// ---------------- 3) scores + causal mask + softmax over QUERY axis ----------------
__global__ void scores_kernel() {
    int k = blockIdx.x, b = blockIdx.y;
    int tid = threadIdx.x;
    __shared__ float kv[H_];
    __shared__ float red[256];
    if (tid < H_) kv[tid] = g_k[(b * S_ + k) * HP + tid];
    __syncthreads();

    float dloc[8];
    float m = -1e30f;
    int cnt = 0;
    for (int q = k + tid; q < S_; q += 256) {
        const float* qp = &g_q[(b * S_ + q) * HP];
        float d = 0.f;
        #pragma unroll
        for (int h = 0; h < H_; h++) d += qp[h] * kv[h];
        dloc[cnt++] = d;
        m = fmaxf(m, d);
    }
    red[tid] = m; __syncthreads();
    #pragma unroll
    for (int s = 128; s > 0; s >>= 1) {
        if (tid < s) red[tid] = fmaxf(red[tid], red[tid + s]);
        __syncthreads();
    }
    float M = red[0]; __syncthreads();

    float ssum = 0.f;
    for (int i = 0; i < cnt; i++) { dloc[i] = expf(dloc[i] - M); ssum += dloc[i]; }
    red[tid] = ssum; __syncthreads();
    #pragma unroll
    for (int s = 128; s > 0; s >>= 1) {
        if (tid < s) red[tid] += red[tid + s];
        __syncthreads();
    }
    float inv = 1.0f / red[0];

    size_t rowbase = ((size_t)b * S_ + k) * S_;
    cnt = 0;
    for (int q = k + tid; q < S_; q += 256) g_att[rowbase + q] = dloc[cnt++] * inv;
    for (int q = tid; q < k; q += 256)      g_att[rowbase + q] = 0.f;
}

// ---------------- 4) res = att @ v  (16 k-chunks, causal early-out) ----------------
__global__ void attv_kernel() {
    int qt = blockIdx.x, kc = blockIdx.y, b = blockIdx.z;
    int tid = threadIdx.x;
    int q = qt * 128 + tid;
    float* dst = &g_part[((kc * R_) + b * S_ + q) * HP];
    if (kc > qt) {                       // fully masked chunk
        #pragma unroll
        for (int h = 0; h < H_; h++) dst[h] = 0.f;
        return;
    }
    __shared__ float vsh[128 * HP];
    int k0 = kc * 128;
    const float* vbase = &g_v[(b * S_ + k0) * HP];
    for (int i = tid; i < 128 * HP; i += 128) vsh[i] = vbase[i];
    __syncthreads();

    float acc[H_];
    #pragma unroll
    for (int h = 0; h < H_; h++) acc[h] = 0.f;

    size_t attbase = ((size_t)b * S_ + k0) * S_ + q;
    for (int kk = 0; kk < 128; kk++) {
        float a = g_att[attbase + (size_t)kk * S_];
        const float* vr = &vsh[kk * HP];
        #pragma unroll
        for (int h = 0; h < H_; h++) acc[h] += a * vr[h];
    }
    #pragma unroll
    for (int h = 0; h < H_; h++) dst[h] = acc[h];
}

// ---------------- 4b) sum partials ----------------
__global__ void reduce_part_kernel() {
    int idx = blockIdx.x * 256 + threadIdx.x;        // [0, R_*HP)
    float s = 0.f;
    #pragma unroll
    for (int p = 0; p < KCH; p++) s += g_part[p * R_ * HP + idx];
    g_res[idx] = s;
}

// ---------------- 5) out = res @ fw + fb ----------------
// phase 0: fp32 to g_h1. phase 1: fp16 (x A_SCALE) into tiled GEMM-A layout.
__global__ void ff_kernel(int phase, const float* __restrict__ fw, const float* __restrict__ fb) {
    int idx = blockIdx.x * 256 + threadIdx.x;
    int r = idx >> 9, d = idx & (D_ - 1);
    float sacc = fb[d];
    #pragma unroll
    for (int h = 0; h < H_; h++) sacc += g_res[r * HP + h] * fw[h * D_ + d];
    if (phase == 0) {
        g_h1[idx] = sacc;
    } else {
        int mt = r >> 7, rrow = r & 127, kc = d >> 5, kk = d & 31;
        size_t off = (((size_t)(mt * NKC + kc) * 128) + rrow) * LDP + kk;
        ((__half*)g_a_hi4)[off] = __float2half(sacc * A_SCALE);
    }
}

// ---------------- 6a) transpose out_w -> tiled fp16 GEMM-B layout ----------------
__global__ void conv_b_kernel(const float* __restrict__ outw) {
    __shared__ float t[32][33];
    int v0 = blockIdx.x * 32, k0 = blockIdx.y * 32;
    int tx = threadIdx.x, ty = threadIdx.y;          // 32 x 8
    #pragma unroll
    for (int j = 0; j < 4; j++) {
        int k = k0 + ty + j * 8;
        t[ty + j * 8][tx] = outw[(size_t)k * V_ + v0 + tx];
    }
    __syncthreads();
    int kc = k0 >> 5;
    #pragma unroll
    for (int j = 0; j < 4; j++) {
        int v = v0 + ty + j * 8;
        float val = t[tx][ty + j * 8] * B_SCALE;     // = outw[k0+tx][v] * 2^6
        int nt = v >> 8, vrow = v & 255;
        size_t off = (((size_t)(nt * NKC + kc) * 256) + vrow) * LDP + tx;
        ((__half*)g_bt_hi4)[off] = __float2half(val);
    }
}

// ---------------- 6b) bulk-copy pipelined fp16 MMA GEMM ----------------
// Tile 128x256, K-chunk 32, 4-stage cp.async.bulk + mbarrier pipeline.
// C = (Ah*Bh) * 2^-10 + bias;  dropped Al*Bh + Ah*Bl ~ 3e-4 relative.
#define B_HI_O TILE_A_BYTES                  // 10240
#define STG_SZ (TILE_A_BYTES + TILE_B_BYTES) // 30720
#define NSTAGE 4
#define CTRL 1024
#define GSMEM (CTRL + NSTAGE * STG_SZ)       // 123904

__device__ __forceinline__ uint32_t smem_u32(const void* p) {
    uint32_t r;
    asm("{ .reg .u64 t; cvta.to.shared.u64 t, %1; cvt.u32.u64 %0, t; }"
        : "=r"(r) : "l"(p));
    return r;
}
__device__ __forceinline__ void bulk_g2s(uint32_t dst, const void* src, uint32_t bytes,
                                         uint32_t mbar) {
    asm volatile(
        "cp.async.bulk.shared::cluster.global.mbarrier::complete_tx::bytes [%0], [%1], %2, [%3];"
        :: "r"(dst), "l"(src), "r"(bytes), "r"(mbar) : "memory");
}
__device__ __forceinline__ void mbar_expect(uint32_t mbar, uint32_t bytes) {
    asm volatile("mbarrier.arrive.expect_tx.shared.b64 _, [%0], %1;"
                 :: "r"(mbar), "r"(bytes) : "memory");
}
__device__ __forceinline__ void mbar_wait(uint32_t addr, uint32_t parity) {
    asm volatile(
        "{\n\t.reg .pred P;\n\t"
        "W_%=:\n\t"
        "mbarrier.try_wait.parity.acquire.cta.shared::cta.b64 P, [%0], %1, 0x989680;\n\t"
        "@P bra.uni D_%=;\n\t"
        "bra.uni W_%=;\n\t"
        "D_%=:\n\t}"
        :: "r"(addr), "r"(parity) : "memory");
}
__device__ __forceinline__ void ldmatrix4(uint32_t* r, uint32_t addr) {
    asm volatile("ldmatrix.sync.aligned.m8n8.x4.shared.b16 {%0,%1,%2,%3}, [%4];"
                 : "=r"(r[0]), "=r"(r[1]), "=r"(r[2]), "=r"(r[3]) : "r"(addr));
}
__device__ __forceinline__ void mma16816(float* c, const uint32_t* a, uint32_t b0, uint32_t b1) {
    asm volatile(
        "mma.sync.aligned.m16n8k16.row.col.f32.f16.f16.f32 "
        "{%0,%1,%2,%3}, {%4,%5,%6,%7}, {%8,%9}, {%0,%1,%2,%3};"
        : "+f"(c[0]), "+f"(c[1]), "+f"(c[2]), "+f"(c[3])
        : "r"(a[0]), "r"(a[1]), "r"(a[2]), "r"(a[3]), "r"(b0), "r"(b1));
}

__global__ __launch_bounds__(256, 1)
void gemm_mma_kernel(const float* __restrict__ bias, float* __restrict__ C) {
    extern __shared__ __align__(16) char smem[];
    uint32_t sb = smem_u32(smem);
    int tid = threadIdx.x;
    int wid = tid >> 5, lid = tid & 31;
    int rowBase = blockIdx.x * 128;
    int colBase = blockIdx.y * 256;

    const char* gAh = (const char*)g_a_hi4 + (size_t)blockIdx.x * NKC * TILE_A_BYTES;
    const char* gBh = (const char*)g_bt_hi4 + (size_t)blockIdx.y * NKC * TILE_B_BYTES;

    if (tid == 0) {
        #pragma unroll
        for (int s = 0; s < NSTAGE; s++)
            asm volatile("mbarrier.init.shared.b64 [%0], 1;" :: "r"(sb + 8u * s) : "memory");
    }
    __syncthreads();

    auto issue = [&](int c, int s) {
        uint32_t mb = sb + 8u * s;
        uint32_t stg = sb + CTRL + (uint32_t)s * STG_SZ;
        mbar_expect(mb, STG_SZ);
        bulk_g2s(stg, gAh + (size_t)c * TILE_A_BYTES, TILE_A_BYTES, mb);
        bulk_g2s(stg + B_HI_O,                    gBh + (size_t)c * TILE_B_BYTES, TILE_B_BYTES / 2, mb);
        bulk_g2s(stg + B_HI_O + TILE_B_BYTES / 2, gBh + (size_t)c * TILE_B_BYTES + TILE_B_BYTES / 2, TILE_B_BYTES / 2, mb);
    };

    if (tid == 0) { issue(0, 0); issue(1, 1); issue(2, 2); issue(3, 3); }

    int warpM = (wid & 1) * 64;       // 2 m-warps
    int warpN = (wid >> 1) * 64;      // 4 n-warps
    int lrow = lid & 15;
    int lk = (lid >> 4) * 8;

    float acc[4][8][4];
    #pragma unroll
    for (int i = 0; i < 4; i++)
        #pragma unroll
        for (int j = 0; j < 8; j++)
            #pragma unroll
            for (int v = 0; v < 4; v++) acc[i][j][v] = 0.f;

    #pragma unroll 1
    for (int c = 0; c < NKC; c++) {
        int s = c % NSTAGE;
        mbar_wait(sb + 8u * s, (c / NSTAGE) & 1);
        uint32_t stg = sb + CTRL + (uint32_t)s * STG_SZ;

        #pragma unroll
        for (int k16 = 0; k16 < 2; k16++) {
            uint32_t a[4][4];
            #pragma unroll
            for (int mi = 0; mi < 4; mi++)
                ldmatrix4(a[mi], stg + ((warpM + mi * 16 + lrow) * LDP + k16 * 16 + lk) * 2);
            uint32_t b[4][4];
            #pragma unroll
            for (int ni = 0; ni < 4; ni++)
                ldmatrix4(b[ni], stg + B_HI_O + ((warpN + ni * 16 + lrow) * LDP + k16 * 16 + lk) * 2);
            #pragma unroll
            for (int mi = 0; mi < 4; mi++)
                #pragma unroll
                for (int nj = 0; nj < 8; nj++) {
                    uint32_t b0 = (nj & 1) ? b[nj >> 1][1] : b[nj >> 1][0];
                    uint32_t b1 = (nj & 1) ? b[nj >> 1][3] : b[nj >> 1][2];
                    mma16816(acc[mi][nj], a[mi], b0, b1);
                }
        }
        __syncthreads();
        if (tid == 0 && c + NSTAGE < NKC) issue(c + NSTAGE, s);
    }

    // ---- epilogue: unscale + bias, direct stores ----
    int g = lid >> 2, tig = lid & 3;
    #pragma unroll
    for (int mi = 0; mi < 4; mi++) {
        #pragma unroll
        for (int nj = 0; nj < 8; nj++) {
            int row = rowBase + warpM + mi * 16 + g;
            int col = colBase + warpN + nj * 8 + tig * 2;
            float2 bv = *(const float2*)&bias[col];
            float2 o0 = { acc[mi][nj][0] * OUT_SCALE + bv.x, acc[mi][nj][1] * OUT_SCALE + bv.y };
            float2 o1 = { acc[mi][nj][2] * OUT_SCALE + bv.x, acc[mi][nj][3] * OUT_SCALE + bv.y };
            *(float2*)&C[(size_t)row * V_ + col] = o0;
            *(float2*)&C[(size_t)(row + 8) * V_ + col] = o1;
        }
    }
}

// ---------------- launch ----------------
extern "C" void kernel_launch(void* const* d_in, const int* in_sizes, int n_in,
                              void* d_out, int out_size) {
    const int*   x    = (const int*)d_in[0];
    const float* tab  = (const float*)d_in[1];
    const float* k1w  = (const float*)d_in[2];
    const float* k1b  = (const float*)d_in[3];
    const float* q1w  = (const float*)d_in[4];
    const float* q1b  = (const float*)d_in[5];
    const float* v1w  = (const float*)d_in[6];
    const float* v1b  = (const float*)d_in[7];
    const float* f1w  = (const float*)d_in[8];
    const float* f1b  = (const float*)d_in[9];
    const float* k2w  = (const float*)d_in[10];
    const float* k2b  = (const float*)d_in[11];
    const float* q2w  = (const float*)d_in[12];
    const float* q2b  = (const float*)d_in[13];
    const float* v2w  = (const float*)d_in[14];
    const float* v2b  = (const float*)d_in[15];
    const float* f2w  = (const float*)d_in[16];
    const float* f2b  = (const float*)d_in[17];
    const float* outw = (const float*)d_in[18];
    const float* outb = (const float*)d_in[19];
    float* out = (float*)d_out;

    cudaFuncSetAttribute(gemm_mma_kernel, cudaFuncAttributeMaxDynamicSharedMemorySize, GSMEM);

    // out_w transpose (fp16, scaled) is independent of everything upstream
    conv_b_kernel<<<dim3(V_ / 32, D_ / 32), dim3(32, 8)>>>(outw);

    embed_kernel<<<(R_ * D_) / 256, 256>>>(x, tab);

    // attention block 1: g_emb -> g_h1
    qkv_kernel<<<R_ / 8, 256>>>(0, k1w, k1b, q1w, q1b, v1w, v1b);
    scores_kernel<<<dim3(S_, B_), 256>>>();
    attv_kernel<<<dim3(16, KCH, 2), 128>>>();
    reduce_part_kernel<<<(R_ * HP) / 256, 256>>>();
    ff_kernel<<<(R_ * D_) / 256, 256>>>(0, f1w, f1b);

    // attention block 2: g_h1 -> tiled fp16 (fused in ff phase 1)
    qkv_kernel<<<R_ / 8, 256>>>(1, k2w, k2b, q2w, q2b, v2w, v2b);
    scores_kernel<<<dim3(S_, B_), 256>>>();
    attv_kernel<<<dim3(16, KCH, 2), 128>>>();
    reduce_part_kernel<<<(R_ * HP) / 256, 256>>>();
    ff_kernel<<<(R_ * D_) / 256, 256>>>(1, f2w, f2b);

    // final vocab projection: bulk-fed fp16 tensor-core GEMM
    gemm_mma_kernel<<<dim3(MT_, NT_), 256, GSMEM>>>(outb, out);
}